// round 3
// baseline (speedup 1.0000x reference)
#include <cuda_runtime.h>
#include <cstdint>

#define NN 50000
#define EMAX 1700000
#define SCAN_B 512
#define NB ((NN + SCAN_B - 1) / SCAN_B)   // 98

// ---------------- scratch (device globals; no allocation allowed) ----------
__device__ float g_xw[(size_t)NN * 512];
__device__ float g_h1[(size_t)NN * 256];
__device__ float g_h2[(size_t)NN * 512];
__device__ float g_h4in[(size_t)NN * 256];
__device__ float g_h4[(size_t)NN * 128];
__device__ float g_dinv[NN];
__device__ int   g_degi[NN];
__device__ int   g_off[NN];
__device__ int   g_cur[NN];
__device__ int   g_bsum[NB];
__device__ int   g_btop[NB];
__device__ int   g_csr[EMAX];
__device__ float g_nrm[EMAX];
__device__ int   g_is64;

// ---------------- edge-format detect ---------------------------------------
__global__ void detect_k(const unsigned int* __restrict__ e) {
    __shared__ int ok;
    if (threadIdx.x == 0) ok = 1;
    __syncthreads();
    for (int i = threadIdx.x; i < 512; i += blockDim.x)
        if (e[2 * i + 1] != 0u) ok = 0;
    __syncthreads();
    if (threadIdx.x == 0) g_is64 = ok;
}

__device__ __forceinline__ void edge_sd(const unsigned int* e, long long E,
                                        long long i, int& s, int& d) {
    if (g_is64) { s = (int)e[2 * i]; d = (int)e[2 * (E + i)]; }
    else        { s = (int)e[i];     d = (int)e[E + i]; }
}

// ---------------- CSR build -------------------------------------------------
__global__ void zero_deg_k() {
    int i = blockIdx.x * blockDim.x + threadIdx.x;
    if (i < NN) g_degi[i] = 0;
}

__global__ void hist_k(const unsigned int* __restrict__ e, long long E) {
    long long i = (long long)blockIdx.x * blockDim.x + threadIdx.x;
    if (i >= E) return;
    int d = g_is64 ? (int)e[2 * (E + i)] : (int)e[E + i];
    atomicAdd(&g_degi[d], 1);
}

__global__ void dinv_k() {
    int i = blockIdx.x * blockDim.x + threadIdx.x;
    if (i < NN) g_dinv[i] = rsqrtf((float)g_degi[i] + 1.0f);
}

__global__ void scan1_k() {
    __shared__ int sh[SCAN_B];
    int i = blockIdx.x * SCAN_B + threadIdx.x;
    int v = (i < NN) ? g_degi[i] : 0;
    sh[threadIdx.x] = v;
    __syncthreads();
#pragma unroll
    for (int o = 1; o < SCAN_B; o <<= 1) {
        int t = (threadIdx.x >= o) ? sh[threadIdx.x - o] : 0;
        __syncthreads();
        sh[threadIdx.x] += t;
        __syncthreads();
    }
    if (i < NN) g_off[i] = sh[threadIdx.x] - v;
    if (threadIdx.x == SCAN_B - 1) g_bsum[blockIdx.x] = sh[SCAN_B - 1];
}

__global__ void scan2_k() {
    if (threadIdx.x == 0) {
        int acc = 0;
        for (int b = 0; b < NB; b++) { int t = g_bsum[b]; g_btop[b] = acc; acc += t; }
    }
}

__global__ void scan3_k() {
    int i = blockIdx.x * blockDim.x + threadIdx.x;
    if (i < NN) {
        int o = g_off[i] + g_btop[i / SCAN_B];
        g_off[i] = o;
        g_cur[i] = o;
    }
}

__global__ void fill_k(const unsigned int* __restrict__ e, long long E) {
    long long i = (long long)blockIdx.x * blockDim.x + threadIdx.x;
    if (i >= E) return;
    int s, d;
    edge_sd(e, E, i, s, d);
    int pos = atomicAdd(&g_cur[d], 1);
    g_csr[pos] = s;
    g_nrm[pos] = g_dinv[s] * g_dinv[d];
}

// ---------------- 3xTF32 tensor-core GEMM -----------------------------------
// C[M,Nn] = A[M,K] @ B[K,Nn], fp32 in/out, 3xTF32 mma.sync path.
// CTA tile 128x128, BK=32, 256 threads = 8 warps, warp tile 64x32.

__device__ __forceinline__ void split_tf32(float a, float& hi, float& lo) {
    hi = __uint_as_float(__float_as_uint(a) & 0xFFFFE000u);
    lo = a - hi;
}

__device__ __forceinline__ void mma_tf32(float* c, uint32_t a0, uint32_t a1,
                                         uint32_t a2, uint32_t a3,
                                         uint32_t b0, uint32_t b1) {
    asm volatile(
        "mma.sync.aligned.m16n8k8.row.col.f32.tf32.tf32.f32 "
        "{%0,%1,%2,%3}, {%4,%5,%6,%7}, {%8,%9}, {%0,%1,%2,%3};\n"
        : "+f"(c[0]), "+f"(c[1]), "+f"(c[2]), "+f"(c[3])
        : "r"(a0), "r"(a1), "r"(a2), "r"(a3), "r"(b0), "r"(b1));
}

// A packed slot (float4): {A[g][t], A[g][t+4], A[g+8][t], A[g+8][t+4]}
//   slot index = ((ks*8 + mt)*8 + g)*4 + t    (ks: kstep 0..3, mt: mtile 0..7)
// B packed slot (float4): {B[16kp+t][n], B[16kp+t+4][n], B[16kp+t+8][n], B[16kp+t+12][n]}
//   slot index = ((kp*16 + nt)*8 + g)*4 + t   (kp: kpair 0..1, nt: ntile 0..15, g: n%8)
#define APK(ks, mt, g, t) ((((ks)*8 + (mt))*8 + (g))*4 + (t))
#define BPK(kp, nt, g, t) ((((kp)*16 + (nt))*8 + (g))*4 + (t))

__global__ __launch_bounds__(256, 1) void gemm3tf32_k(
    const float* __restrict__ A, const float* __restrict__ B,
    float* __restrict__ C, int M, int Nn, int K)
{
    __shared__ float4 Ahi[1024];   // 16 KB
    __shared__ float4 Alo[1024];   // 16 KB
    __shared__ float4 Bpk[1024];   // 16 KB (unsplit)

    int tid = threadIdx.x;
    int lane = tid & 31;
    int warp = tid >> 5;
    int g = lane >> 2;
    int t = lane & 3;
    int wm = warp & 1;      // 0..1, 64-row slab
    int wn = warp >> 1;     // 0..3, 32-col slab
    int rowBase = blockIdx.y * 128;
    int colBase = blockIdx.x * 128;

    float acc[4][4][4];
#pragma unroll
    for (int i = 0; i < 4; i++)
#pragma unroll
        for (int j = 0; j < 4; j++)
#pragma unroll
            for (int q = 0; q < 4; q++) acc[i][j][q] = 0.0f;

    // ldg staging: 4 A float4 + 4 B float4 per thread
    float4 stA[4], stB[4];

    // A ldg coords: f4 idx = tid + it*256 -> row = idx>>3, c4 = idx&7
    // B ldg coords: f4 idx = tid + it*256 -> k = idx>>5, c4 = idx&31
    auto ldgA = [&](int k0) {
#pragma unroll
        for (int it = 0; it < 4; it++) {
            int idx = tid + it * 256;
            int row = idx >> 3, c4 = idx & 7;
            int gr = rowBase + row;
            stA[it] = (gr < M) ? *(const float4*)&A[(size_t)gr * K + k0 + c4 * 4]
                               : make_float4(0.f, 0.f, 0.f, 0.f);
        }
    };
    auto ldgB = [&](int k0) {
#pragma unroll
        for (int it = 0; it < 4; it++) {
            int idx = tid + it * 256;
            int k = idx >> 5, c4 = idx & 31;
            stB[it] = *(const float4*)&B[(size_t)(k0 + k) * Nn + colBase + c4 * 4];
        }
    };
    auto stsAB = [&]() {
#pragma unroll
        for (int it = 0; it < 4; it++) {
            int idx = tid + it * 256;
            {   // A: split into Ahi/Alo packed
                int row = idx >> 3, c4 = idx & 7;
                int mt = row >> 4, gp = row & 15;
                int gg = gp & 7;
                const float* v = &stA[it].x;
#pragma unroll
                for (int cc = 0; cc < 4; cc++) {
                    int k = c4 * 4 + cc;
                    int ks = k >> 3, tt = k & 3, hk = (k >> 2) & 1;
                    int comp = (gp < 8) ? hk : 2 + hk;
                    float hi, lo;
                    split_tf32(v[cc], hi, lo);
                    ((float*)&Ahi[APK(ks, mt, gg, tt)])[comp] = hi;
                    ((float*)&Alo[APK(ks, mt, gg, tt)])[comp] = lo;
                }
            }
            {   // B: packed, unsplit
                int k = idx >> 5, c4 = idx & 31;
                int kp = k >> 4, tt = k & 3, comp = (k >> 2) & 3;
                const float* v = &stB[it].x;
#pragma unroll
                for (int cc = 0; cc < 4; cc++) {
                    int n = c4 * 4 + cc;
                    ((float*)&Bpk[BPK(kp, n >> 3, n & 7, tt)])[comp] = v[cc];
                }
            }
        }
    };

    ldgA(0); ldgB(0);

    for (int k0 = 0; k0 < K; k0 += 32) {
        stsAB();
        __syncthreads();
        if (k0 + 32 < K) { ldgA(k0 + 32); ldgB(k0 + 32); }

#pragma unroll
        for (int kp = 0; kp < 2; kp++) {
            // B fragments for both ksteps of this kpair, split in registers
            uint32_t bh[4][4], bl[4][4];
#pragma unroll
            for (int j = 0; j < 4; j++) {
                float4 b = Bpk[BPK(kp, wn * 4 + j, g, t)];
                const float* bv = &b.x;
#pragma unroll
                for (int q = 0; q < 4; q++) {
                    float hi, lo;
                    split_tf32(bv[q], hi, lo);
                    bh[j][q] = __float_as_uint(hi);
                    bl[j][q] = __float_as_uint(lo);
                }
            }
#pragma unroll
            for (int ks2 = 0; ks2 < 2; ks2++) {
                int ks = kp * 2 + ks2;
                float4 ah[4], al[4];
#pragma unroll
                for (int i = 0; i < 4; i++) {
                    ah[i] = Ahi[APK(ks, wm * 4 + i, g, t)];
                    al[i] = Alo[APK(ks, wm * 4 + i, g, t)];
                }
#pragma unroll
                for (int i = 0; i < 4; i++) {
                    // operand order a0,a1,a2,a3 = (x, z, y, w)
                    uint32_t ah0 = __float_as_uint(ah[i].x), ah1 = __float_as_uint(ah[i].z);
                    uint32_t ah2 = __float_as_uint(ah[i].y), ah3 = __float_as_uint(ah[i].w);
                    uint32_t al0 = __float_as_uint(al[i].x), al1 = __float_as_uint(al[i].z);
                    uint32_t al2 = __float_as_uint(al[i].y), al3 = __float_as_uint(al[i].w);
#pragma unroll
                    for (int j = 0; j < 4; j++) {
                        uint32_t b0h = ks2 ? bh[j][2] : bh[j][0];
                        uint32_t b1h = ks2 ? bh[j][3] : bh[j][1];
                        uint32_t b0l = ks2 ? bl[j][2] : bl[j][0];
                        uint32_t b1l = ks2 ? bl[j][3] : bl[j][1];
                        mma_tf32(acc[i][j], ah0, ah1, ah2, ah3, b0h, b1h);  // hi*hi
                        mma_tf32(acc[i][j], al0, al1, al2, al3, b0h, b1h);  // lo*hi
                        mma_tf32(acc[i][j], ah0, ah1, ah2, ah3, b0l, b1l);  // hi*lo
                    }
                }
            }
        }
        __syncthreads();
    }

    // epilogue: c0,c1 at (row g, col 2t), c2,c3 at (row g+8, col 2t)
#pragma unroll
    for (int i = 0; i < 4; i++) {
        int r0 = rowBase + wm * 64 + i * 16 + g;
        int r1 = r0 + 8;
#pragma unroll
        for (int j = 0; j < 4; j++) {
            int col = colBase + wn * 32 + j * 8 + t * 2;
            if (r0 < M) *(float2*)&C[(size_t)r0 * Nn + col] =
                make_float2(acc[i][j][0], acc[i][j][1]);
            if (r1 < M) *(float2*)&C[(size_t)r1 * Nn + col] =
                make_float2(acc[i][j][2], acc[i][j][3]);
        }
    }
}

// ---------------- fused warp-per-node: CSR gather + self + bias + LN + ELU --
template<int F>
__global__ __launch_bounds__(256) void agg_ln_elu_k(
    const float* __restrict__ xw,
    const float* __restrict__ bias,
    const float* __restrict__ gamma,
    const float* __restrict__ beta,
    float* __restrict__ out,
    const float* __restrict__ resid,
    float* __restrict__ out_raw,
    float* __restrict__ out_bn)
{
    constexpr int RF = F / 128;
    int warp = (blockIdx.x * blockDim.x + threadIdx.x) >> 5;
    int lane = threadIdx.x & 31;
    if (warp >= NN) return;
    int d = warp;

    float4 acc[RF];
#pragma unroll
    for (int i = 0; i < RF; i++) acc[i] = make_float4(0.f, 0.f, 0.f, 0.f);

    int beg = g_off[d];
    int cnt = g_degi[d];

    for (int b0 = 0; b0 < cnt; b0 += 32) {
        int n = min(32, cnt - b0);
        int   s_l = 0;
        float n_l = 0.f;
        if (lane < n) {
            s_l = g_csr[beg + b0 + lane];
            n_l = g_nrm[beg + b0 + lane];
        }
        for (int j = 0; j < n; j++) {
            int   s   = __shfl_sync(0xffffffffu, s_l, j);
            float nrm = __shfl_sync(0xffffffffu, n_l, j);
            const float4* row = (const float4*)(xw + (size_t)s * F);
#pragma unroll
            for (int i = 0; i < RF; i++) {
                float4 v = row[i * 32 + lane];
                acc[i].x = fmaf(nrm, v.x, acc[i].x);
                acc[i].y = fmaf(nrm, v.y, acc[i].y);
                acc[i].z = fmaf(nrm, v.z, acc[i].z);
                acc[i].w = fmaf(nrm, v.w, acc[i].w);
            }
        }
    }

    {
        float dd = g_dinv[d];
        float nrm = dd * dd;
        const float4* row = (const float4*)(xw + (size_t)d * F);
        const float4* bb  = (const float4*)bias;
#pragma unroll
        for (int i = 0; i < RF; i++) {
            float4 v = row[i * 32 + lane];
            float4 b = bb[i * 32 + lane];
            acc[i].x = fmaf(nrm, v.x, acc[i].x) + b.x;
            acc[i].y = fmaf(nrm, v.y, acc[i].y) + b.y;
            acc[i].z = fmaf(nrm, v.z, acc[i].z) + b.z;
            acc[i].w = fmaf(nrm, v.w, acc[i].w) + b.w;
        }
    }

    float s = 0.f, q = 0.f;
#pragma unroll
    for (int i = 0; i < RF; i++) {
        s += acc[i].x + acc[i].y + acc[i].z + acc[i].w;
        q += acc[i].x * acc[i].x + acc[i].y * acc[i].y
           + acc[i].z * acc[i].z + acc[i].w * acc[i].w;
    }
#pragma unroll
    for (int o = 16; o > 0; o >>= 1) {
        s += __shfl_xor_sync(0xffffffffu, s, o);
        q += __shfl_xor_sync(0xffffffffu, q, o);
    }
    constexpr float invF = 1.0f / F;
    float mu = s * invF;
    float var = q * invF - mu * mu;
    float rstd = rsqrtf(var + 1e-5f);

    const float4* gp = (const float4*)gamma;
    const float4* bp = (const float4*)beta;
    float4* op = (float4*)(out + (size_t)d * F);
    const float4* rp = resid ? (const float4*)(resid + (size_t)d * F) : nullptr;
    float4* rawp = out_raw ? (float4*)(out_raw + (size_t)d * F) : nullptr;
    float4* bnp  = out_bn  ? (float4*)(out_bn  + (size_t)d * F) : nullptr;

#pragma unroll
    for (int i = 0; i < RF; i++) {
        int idx = i * 32 + lane;
        float4 gv = gp[idx];
        float4 bv = bp[idx];
        float4 y;
        y.x = (acc[i].x - mu) * rstd * gv.x + bv.x;
        y.y = (acc[i].y - mu) * rstd * gv.y + bv.y;
        y.z = (acc[i].z - mu) * rstd * gv.z + bv.z;
        y.w = (acc[i].w - mu) * rstd * gv.w + bv.w;
        if (rawp) rawp[idx] = acc[i];
        if (bnp)  bnp[idx]  = y;
        float4 eo;
        eo.x = y.x > 0.f ? y.x : expm1f(y.x);
        eo.y = y.y > 0.f ? y.y : expm1f(y.y);
        eo.z = y.z > 0.f ? y.z : expm1f(y.z);
        eo.w = y.w > 0.f ? y.w : expm1f(y.w);
        if (rp) {
            float4 r = rp[idx];
            eo.x += r.x; eo.y += r.y; eo.z += r.z; eo.w += r.w;
        }
        op[idx] = eo;
    }
}

// ---------------- classifier: [N,128] @ [128,4] + bc -----------------------
__global__ void classifier_k(const float* __restrict__ h,
                             const float* __restrict__ Wc,
                             const float* __restrict__ bc,
                             float* __restrict__ out) {
    int warp = (blockIdx.x * blockDim.x + threadIdx.x) >> 5;
    int lane = threadIdx.x & 31;
    if (warp >= NN) return;
    const float* row = h + (size_t)warp * 128;
    float a0 = 0.f, a1 = 0.f, a2 = 0.f, a3 = 0.f;
    for (int k = lane; k < 128; k += 32) {
        float v = row[k];
        a0 += v * Wc[k * 4 + 0];
        a1 += v * Wc[k * 4 + 1];
        a2 += v * Wc[k * 4 + 2];
        a3 += v * Wc[k * 4 + 3];
    }
#pragma unroll
    for (int o = 16; o > 0; o >>= 1) {
        a0 += __shfl_down_sync(0xffffffffu, a0, o);
        a1 += __shfl_down_sync(0xffffffffu, a1, o);
        a2 += __shfl_down_sync(0xffffffffu, a2, o);
        a3 += __shfl_down_sync(0xffffffffu, a3, o);
    }
    if (lane == 0) {
        out[(size_t)warp * 4 + 0] = a0 + bc[0];
        out[(size_t)warp * 4 + 1] = a1 + bc[1];
        out[(size_t)warp * 4 + 2] = a2 + bc[2];
        out[(size_t)warp * 4 + 3] = a3 + bc[3];
    }
}

// ---------------- host launch ----------------------------------------------
static inline void* sym(const void* s) {
    void* p = nullptr;
    cudaGetSymbolAddress(&p, s);
    return p;
}

extern "C" void kernel_launch(void* const* d_in, const int* in_sizes, int n_in,
                              void* d_out, int out_size) {
    const float* x  = (const float*)d_in[0];
    const unsigned int* e = (const unsigned int*)d_in[1];
    const float* W1 = (const float*)d_in[2];  const float* b1 = (const float*)d_in[3];
    const float* W2 = (const float*)d_in[4];  const float* b2 = (const float*)d_in[5];
    const float* W3 = (const float*)d_in[6];  const float* b3 = (const float*)d_in[7];
    const float* W4 = (const float*)d_in[8];  const float* b4 = (const float*)d_in[9];
    const float* Wc = (const float*)d_in[10]; const float* bc = (const float*)d_in[11];
    const float* g1 = (const float*)d_in[12]; const float* be1 = (const float*)d_in[13];
    const float* g2 = (const float*)d_in[14]; const float* be2 = (const float*)d_in[15];
    const float* g3 = (const float*)d_in[16]; const float* be3 = (const float*)d_in[17];
    const float* g4 = (const float*)d_in[18]; const float* be4 = (const float*)d_in[19];

    long long E = (long long)in_sizes[1] / 2;

    float* out        = (float*)d_out;
    float* out_logits = out;
    float* out_conv   = out + (size_t)NN * 4;
    float* out_bn     = out_conv + (size_t)NN * 128;

    float* xw   = (float*)sym(g_xw);
    float* h1   = (float*)sym(g_h1);
    float* h2   = (float*)sym(g_h2);
    float* h4in = (float*)sym(g_h4in);
    float* h4   = (float*)sym(g_h4);

    // ---- CSR build (per replay) ----
    detect_k<<<1, 256>>>(e);
    zero_deg_k<<<(NN + 255) / 256, 256>>>();
    hist_k<<<(unsigned)((E + 255) / 256), 256>>>(e, E);
    dinv_k<<<(NN + 255) / 256, 256>>>();
    scan1_k<<<NB, SCAN_B>>>();
    scan2_k<<<1, 32>>>();
    scan3_k<<<(NN + 255) / 256, 256>>>();
    fill_k<<<(unsigned)((E + 255) / 256), 256>>>(e, E);

    int mgrid = (NN + 127) / 128;
    unsigned agg_blocks = (NN * 32 + 255) / 256;

    // ---- layer 1: x[.,512] @ W1[512,256] ----
    gemm3tf32_k<<<dim3(2, mgrid), 256>>>(x, W1, xw, NN, 256, 512);
    agg_ln_elu_k<256><<<agg_blocks, 256>>>(xw, b1, g1, be1, h1, nullptr, nullptr, nullptr);

    // ---- layer 2: h1[.,256] @ W2[256,512] ----
    gemm3tf32_k<<<dim3(4, mgrid), 256>>>(h1, W2, xw, NN, 512, 256);
    agg_ln_elu_k<512><<<agg_blocks, 256>>>(xw, b2, g2, be2, h2, nullptr, nullptr, nullptr);

    // ---- layer 3: h2[.,512] @ W3[512,256]; fused residual + h1 ----
    gemm3tf32_k<<<dim3(2, mgrid), 256>>>(h2, W3, xw, NN, 256, 512);
    agg_ln_elu_k<256><<<agg_blocks, 256>>>(xw, b3, g3, be3, h4in, h1, nullptr, nullptr);

    // ---- layer 4: h4in[.,256] @ W4[256,128]; taps out_conv/out_bn ----
    gemm3tf32_k<<<dim3(1, mgrid), 256>>>(h4in, W4, xw, NN, 128, 256);
    agg_ln_elu_k<128><<<agg_blocks, 256>>>(xw, b4, g4, be4, h4, nullptr, out_conv, out_bn);

    // ---- classifier ----
    classifier_k<<<(NN * 32 + 127) / 128, 128>>>(h4, Wc, bc, out_logits);
}

// round 5
// speedup vs baseline: 1.9164x; 1.9164x over previous
#include <cuda_runtime.h>
#include <cuda_bf16.h>
#include <cstdint>

#define NN 50000
#define EMAX 1700000
#define SCAN_B 512
#define NB ((NN + SCAN_B - 1) / SCAN_B)   // 98

// ---------------- scratch (device globals; no allocation allowed) ----------
__device__ float g_xw[(size_t)NN * 512];
__device__ float g_h1[(size_t)NN * 256];
__device__ float g_h2[(size_t)NN * 512];
__device__ float g_h4in[(size_t)NN * 256];
__device__ float g_h4[(size_t)NN * 128];
__device__ float g_dinv[NN];
__device__ int   g_degi[NN];
__device__ int   g_off[NN];
__device__ int   g_cur[NN];
__device__ int   g_bsum[NB];
__device__ int   g_btop[NB];
__device__ int   g_csr[EMAX];
__device__ float g_nrm[EMAX];
__device__ int   g_is64;
__device__ __nv_bfloat16 g_whi[425984];   // K-major transposed weights, hi bf16
__device__ __nv_bfloat16 g_wlo[425984];   // lo bf16

// ---------------- helpers ---------------------------------------------------
__device__ __forceinline__ uint32_t pack_bf16(float a, float b) {
    __nv_bfloat162 v = __floats2bfloat162_rn(a, b);   // .x=a (low), .y=b (high)
    return *reinterpret_cast<uint32_t*>(&v);
}
__device__ __forceinline__ void split_bf16(float a, float& hi, float& lo) {
    __nv_bfloat16 h = __float2bfloat16_rn(a);
    hi = __bfloat162float(h);
    lo = a - hi;
}
__device__ __forceinline__ void mma_bf16(float* c, uint32_t a0, uint32_t a1,
                                         uint32_t a2, uint32_t a3,
                                         uint32_t b0, uint32_t b1) {
    asm volatile(
        "mma.sync.aligned.m16n8k16.row.col.f32.bf16.bf16.f32 "
        "{%0,%1,%2,%3}, {%4,%5,%6,%7}, {%8,%9}, {%0,%1,%2,%3};\n"
        : "+f"(c[0]), "+f"(c[1]), "+f"(c[2]), "+f"(c[3])
        : "r"(a0), "r"(a1), "r"(a2), "r"(a3), "r"(b0), "r"(b1));
}

// ---------------- edge-format detect ---------------------------------------
__global__ void detect_k(const unsigned int* __restrict__ e) {
    __shared__ int ok;
    if (threadIdx.x == 0) ok = 1;
    __syncthreads();
    for (int i = threadIdx.x; i < 512; i += blockDim.x)
        if (e[2 * i + 1] != 0u) ok = 0;
    __syncthreads();
    if (threadIdx.x == 0) g_is64 = ok;
}

__device__ __forceinline__ void edge_sd(const unsigned int* e, long long E,
                                        long long i, int& s, int& d) {
    if (g_is64) { s = (int)e[2 * i]; d = (int)e[2 * (E + i)]; }
    else        { s = (int)e[i];     d = (int)e[E + i]; }
}

// ---------------- CSR build -------------------------------------------------
__global__ void zero_deg_k() {
    int i = blockIdx.x * blockDim.x + threadIdx.x;
    if (i < NN) g_degi[i] = 0;
}
__global__ void hist_k(const unsigned int* __restrict__ e, long long E) {
    long long i = (long long)blockIdx.x * blockDim.x + threadIdx.x;
    if (i >= E) return;
    int d = g_is64 ? (int)e[2 * (E + i)] : (int)e[E + i];
    atomicAdd(&g_degi[d], 1);
}
__global__ void dinv_k() {
    int i = blockIdx.x * blockDim.x + threadIdx.x;
    if (i < NN) g_dinv[i] = rsqrtf((float)g_degi[i] + 1.0f);
}
__global__ void scan1_k() {
    __shared__ int sh[SCAN_B];
    int i = blockIdx.x * SCAN_B + threadIdx.x;
    int v = (i < NN) ? g_degi[i] : 0;
    sh[threadIdx.x] = v;
    __syncthreads();
#pragma unroll
    for (int o = 1; o < SCAN_B; o <<= 1) {
        int t = (threadIdx.x >= o) ? sh[threadIdx.x - o] : 0;
        __syncthreads();
        sh[threadIdx.x] += t;
        __syncthreads();
    }
    if (i < NN) g_off[i] = sh[threadIdx.x] - v;
    if (threadIdx.x == SCAN_B - 1) g_bsum[blockIdx.x] = sh[SCAN_B - 1];
}
__global__ void scan2_k() {
    if (threadIdx.x == 0) {
        int acc = 0;
        for (int b = 0; b < NB; b++) { int t = g_bsum[b]; g_btop[b] = acc; acc += t; }
    }
}
__global__ void scan3_k() {
    int i = blockIdx.x * blockDim.x + threadIdx.x;
    if (i < NN) {
        int o = g_off[i] + g_btop[i / SCAN_B];
        g_off[i] = o;
        g_cur[i] = o;
    }
}
__global__ void fill_k(const unsigned int* __restrict__ e, long long E) {
    long long i = (long long)blockIdx.x * blockDim.x + threadIdx.x;
    if (i >= E) return;
    int s, d;
    edge_sd(e, E, i, s, d);
    int pos = atomicAdd(&g_cur[d], 1);
    g_csr[pos] = s;
    g_nrm[pos] = g_dinv[s] * g_dinv[d];
}

// ---------------- weight transpose + bf16 split -----------------------------
// W[Kd,Nd] row-major -> [Nd,Kd] K-major, split into hi/lo bf16.
__global__ void wsplit_k(const float* __restrict__ W, int Kd, int Nd, int off) {
    int i = blockIdx.x * blockDim.x + threadIdx.x;
    if (i >= Kd * Nd) return;
    int k = i / Nd, n = i - k * Nd;
    float a = W[i];
    float hi, lo;
    split_bf16(a, hi, lo);
    g_whi[off + (size_t)n * Kd + k] = __float2bfloat16_rn(hi);
    g_wlo[off + (size_t)n * Kd + k] = __float2bfloat16_rn(lo);
}

// ---------------- 3xBF16 tensor-core GEMM -----------------------------------
// C[M,Nn] = A[M,K] @ Wt^T, Wt [Nn,K] K-major pre-split hi/lo bf16.
// CTA tile 128x128, BK=32 (2 k16 steps), 8 warps (2m x 4n), warp tile 64x32.
// A split hi/lo bf16 at STS. Packed fragment layouts: one LDS.128 per fragment.
//
// A pack:  Apk[part][ ((ks*8+mt)*8+g)*16 + t*4 + reg ]  (uint32)
//   reg: 0=a0(row g,k-lo) 1=a1(row g+8,k-lo) 2=a2(row g,k-hi) 3=a3(row g+8,k-hi)
// B pack:  Bpk[part][ ((nt*8+g)*4+t)*4 + ks*2 + reg ]   (uint32)
//   frag uint4 = {b0_ks0, b1_ks0, b0_ks1, b1_ks1}

__global__ __launch_bounds__(256, 1) void gemm_bf16x2_k(
    const float* __restrict__ A,
    const __nv_bfloat16* __restrict__ Bhi, const __nv_bfloat16* __restrict__ Blo,
    float* __restrict__ C, int M, int Nn, int K)
{
    __shared__ uint32_t Apk[2][2048];   // 8 KB each
    __shared__ uint32_t Bpk[2][2048];   // 8 KB each

    int tid = threadIdx.x;
    int lane = tid & 31;
    int warp = tid >> 5;
    int g = lane >> 2;
    int t = lane & 3;
    int wm = warp & 1;      // 64-row slab
    int wn = warp >> 1;     // 32-col slab
    int rowBase = blockIdx.y * 128;
    int colBase = blockIdx.x * 128;

    float acc[4][4][4];
#pragma unroll
    for (int i = 0; i < 4; i++)
#pragma unroll
        for (int j = 0; j < 4; j++)
#pragma unroll
            for (int q = 0; q < 4; q++) acc[i][j][q] = 0.0f;

    float4 stA[4];
    uint4  stB[2][2];

    auto ldg = [&](int k0) {
#pragma unroll
        for (int i = 0; i < 4; i++) {
            int idx = tid + i * 256;
            int row = idx >> 3, c4 = idx & 7;
            int gr = rowBase + row;
            stA[i] = (gr < M) ? *(const float4*)&A[(size_t)gr * K + k0 + c4 * 4]
                              : make_float4(0.f, 0.f, 0.f, 0.f);
        }
#pragma unroll
        for (int i = 0; i < 2; i++) {
            int idx = tid + i * 256;
            int n = idx >> 2, w4 = idx & 3;
            size_t go = (size_t)(colBase + n) * K + k0 + w4 * 8;
            stB[0][i] = *(const uint4*)&Bhi[go];
            stB[1][i] = *(const uint4*)&Blo[go];
        }
    };
    auto sts = [&]() {
#pragma unroll
        for (int i = 0; i < 4; i++) {
            int idx = tid + i * 256;
            int row = idx >> 3, c4 = idx & 7;
            int c = c4 * 4;
            int mt = row >> 4, rr = row & 15;
            int gg = rr & 7, h = rr >> 3;
            int ks = c >> 4, kk = c & 15;
            int khalf = kk >> 3;
            int t0 = (kk & 7) >> 1;          // 0 or 2
            int reg = h + 2 * khalf;
            int base = ((ks * 8 + mt) * 8 + gg) * 16 + reg;
            float h0, l0, h1, l1, h2, l2, h3, l3;
            split_bf16(stA[i].x, h0, l0); split_bf16(stA[i].y, h1, l1);
            split_bf16(stA[i].z, h2, l2); split_bf16(stA[i].w, h3, l3);
            Apk[0][base + t0 * 4]       = pack_bf16(h0, h1);
            Apk[0][base + (t0 + 1) * 4] = pack_bf16(h2, h3);
            Apk[1][base + t0 * 4]       = pack_bf16(l0, l1);
            Apk[1][base + (t0 + 1) * 4] = pack_bf16(l2, l3);
        }
#pragma unroll
        for (int i = 0; i < 2; i++) {
            int idx = tid + i * 256;
            int n = idx >> 2, w4 = idx & 3;
            int nt = n >> 3, gg = n & 7;
#pragma unroll
            for (int p = 0; p < 2; p++) {
                const uint32_t* w = (const uint32_t*)&stB[p][i];
#pragma unroll
                for (int wd = 0; wd < 4; wd++) {
                    int k = w4 * 8 + 2 * wd;
                    int ks = k >> 4, kk = k & 15;
                    int tt = (kk >> 1) & 3, reg = kk >> 3;
                    Bpk[p][((nt * 8 + gg) * 4 + tt) * 4 + ks * 2 + reg] = w[wd];
                }
            }
        }
    };

    ldg(0);
    for (int k0 = 0; k0 < K; k0 += 32) {
        sts();
        __syncthreads();
        if (k0 + 32 < K) ldg(k0 + 32);

        // B fragments: both parts, both ksteps, 4 ntiles
        uint4 bh[4], bl[4];
#pragma unroll
        for (int j = 0; j < 4; j++) {
            int o = (((wn * 4 + j) * 8 + g) * 4 + t) * 4;
            bh[j] = *(uint4*)&Bpk[0][o];
            bl[j] = *(uint4*)&Bpk[1][o];
        }
#pragma unroll
        for (int ks = 0; ks < 2; ks++) {
            uint4 ah[4];
#pragma unroll
            for (int i = 0; i < 4; i++)
                ah[i] = *(uint4*)&Apk[0][((ks * 8 + wm * 4 + i) * 8 + g) * 16 + t * 4];
#pragma unroll
            for (int i = 0; i < 4; i++)
#pragma unroll
                for (int j = 0; j < 4; j++) {
                    uint32_t b0 = ks ? bh[j].z : bh[j].x;
                    uint32_t b1 = ks ? bh[j].w : bh[j].y;
                    mma_bf16(acc[i][j], ah[i].x, ah[i].y, ah[i].z, ah[i].w, b0, b1);
                }
#pragma unroll
            for (int i = 0; i < 4; i++)
#pragma unroll
                for (int j = 0; j < 4; j++) {
                    uint32_t b0 = ks ? bl[j].z : bl[j].x;
                    uint32_t b1 = ks ? bl[j].w : bl[j].y;
                    mma_bf16(acc[i][j], ah[i].x, ah[i].y, ah[i].z, ah[i].w, b0, b1);
                }
            uint4 al[4];
#pragma unroll
            for (int i = 0; i < 4; i++)
                al[i] = *(uint4*)&Apk[1][((ks * 8 + wm * 4 + i) * 8 + g) * 16 + t * 4];
#pragma unroll
            for (int i = 0; i < 4; i++)
#pragma unroll
                for (int j = 0; j < 4; j++) {
                    uint32_t b0 = ks ? bh[j].z : bh[j].x;
                    uint32_t b1 = ks ? bh[j].w : bh[j].y;
                    mma_bf16(acc[i][j], al[i].x, al[i].y, al[i].z, al[i].w, b0, b1);
                }
        }
        __syncthreads();
    }

    // epilogue: c0,c1 at (row g, col 2t..2t+1), c2,c3 at (row g+8)
#pragma unroll
    for (int i = 0; i < 4; i++) {
        int r0 = rowBase + wm * 64 + i * 16 + g;
        int r1 = r0 + 8;
#pragma unroll
        for (int j = 0; j < 4; j++) {
            int col = colBase + wn * 32 + j * 8 + t * 2;
            if (r0 < M) *(float2*)&C[(size_t)r0 * Nn + col] =
                make_float2(acc[i][j][0], acc[i][j][1]);
            if (r1 < M) *(float2*)&C[(size_t)r1 * Nn + col] =
                make_float2(acc[i][j][2], acc[i][j][3]);
        }
    }
}

// ---------------- fused warp-per-node: CSR gather + self + bias + LN + ELU --
template<int F>
__global__ __launch_bounds__(256) void agg_ln_elu_k(
    const float* __restrict__ xw,
    const float* __restrict__ bias,
    const float* __restrict__ gamma,
    const float* __restrict__ beta,
    float* __restrict__ out,
    const float* __restrict__ resid,
    float* __restrict__ out_raw,
    float* __restrict__ out_bn)
{
    constexpr int RF = F / 128;
    int warp = (blockIdx.x * blockDim.x + threadIdx.x) >> 5;
    int lane = threadIdx.x & 31;
    if (warp >= NN) return;
    int d = warp;

    float4 acc[RF];
#pragma unroll
    for (int i = 0; i < RF; i++) acc[i] = make_float4(0.f, 0.f, 0.f, 0.f);

    int beg = g_off[d];
    int cnt = g_degi[d];

    for (int b0 = 0; b0 < cnt; b0 += 32) {
        int n = min(32, cnt - b0);
        int   s_l = 0;
        float n_l = 0.f;
        if (lane < n) {
            s_l = g_csr[beg + b0 + lane];
            n_l = g_nrm[beg + b0 + lane];
        }
        for (int j = 0; j < n; j++) {
            int   s   = __shfl_sync(0xffffffffu, s_l, j);
            float nrm = __shfl_sync(0xffffffffu, n_l, j);
            const float4* row = (const float4*)(xw + (size_t)s * F);
#pragma unroll
            for (int i = 0; i < RF; i++) {
                float4 v = row[i * 32 + lane];
                acc[i].x = fmaf(nrm, v.x, acc[i].x);
                acc[i].y = fmaf(nrm, v.y, acc[i].y);
                acc[i].z = fmaf(nrm, v.z, acc[i].z);
                acc[i].w = fmaf(nrm, v.w, acc[i].w);
            }
        }
    }

    {
        float dd = g_dinv[d];
        float nrm = dd * dd;
        const float4* row = (const float4*)(xw + (size_t)d * F);
        const float4* bb  = (const float4*)bias;
#pragma unroll
        for (int i = 0; i < RF; i++) {
            float4 v = row[i * 32 + lane];
            float4 b = bb[i * 32 + lane];
            acc[i].x = fmaf(nrm, v.x, acc[i].x) + b.x;
            acc[i].y = fmaf(nrm, v.y, acc[i].y) + b.y;
            acc[i].z = fmaf(nrm, v.z, acc[i].z) + b.z;
            acc[i].w = fmaf(nrm, v.w, acc[i].w) + b.w;
        }
    }

    float s = 0.f, q = 0.f;
#pragma unroll
    for (int i = 0; i < RF; i++) {
        s += acc[i].x + acc[i].y + acc[i].z + acc[i].w;
        q += acc[i].x * acc[i].x + acc[i].y * acc[i].y
           + acc[i].z * acc[i].z + acc[i].w * acc[i].w;
    }
#pragma unroll
    for (int o = 16; o > 0; o >>= 1) {
        s += __shfl_xor_sync(0xffffffffu, s, o);
        q += __shfl_xor_sync(0xffffffffu, q, o);
    }
    constexpr float invF = 1.0f / F;
    float mu = s * invF;
    float var = q * invF - mu * mu;
    float rstd = rsqrtf(var + 1e-5f);

    const float4* gp = (const float4*)gamma;
    const float4* bp = (const float4*)beta;
    float4* op = (float4*)(out + (size_t)d * F);
    const float4* rp = resid ? (const float4*)(resid + (size_t)d * F) : nullptr;
    float4* rawp = out_raw ? (float4*)(out_raw + (size_t)d * F) : nullptr;
    float4* bnp  = out_bn  ? (float4*)(out_bn  + (size_t)d * F) : nullptr;

#pragma unroll
    for (int i = 0; i < RF; i++) {
        int idx = i * 32 + lane;
        float4 gv = gp[idx];
        float4 bv = bp[idx];
        float4 y;
        y.x = (acc[i].x - mu) * rstd * gv.x + bv.x;
        y.y = (acc[i].y - mu) * rstd * gv.y + bv.y;
        y.z = (acc[i].z - mu) * rstd * gv.z + bv.z;
        y.w = (acc[i].w - mu) * rstd * gv.w + bv.w;
        if (rawp) rawp[idx] = acc[i];
        if (bnp)  bnp[idx]  = y;
        float4 eo;
        eo.x = y.x > 0.f ? y.x : expm1f(y.x);
        eo.y = y.y > 0.f ? y.y : expm1f(y.y);
        eo.z = y.z > 0.f ? y.z : expm1f(y.z);
        eo.w = y.w > 0.f ? y.w : expm1f(y.w);
        if (rp) {
            float4 r = rp[idx];
            eo.x += r.x; eo.y += r.y; eo.z += r.z; eo.w += r.w;
        }
        op[idx] = eo;
    }
}

// ---------------- classifier: [N,128] @ [128,4] + bc -----------------------
__global__ void classifier_k(const float* __restrict__ h,
                             const float* __restrict__ Wc,
                             const float* __restrict__ bc,
                             float* __restrict__ out) {
    int warp = (blockIdx.x * blockDim.x + threadIdx.x) >> 5;
    int lane = threadIdx.x & 31;
    if (warp >= NN) return;
    const float* row = h + (size_t)warp * 128;
    float a0 = 0.f, a1 = 0.f, a2 = 0.f, a3 = 0.f;
    for (int k = lane; k < 128; k += 32) {
        float v = row[k];
        a0 += v * Wc[k * 4 + 0];
        a1 += v * Wc[k * 4 + 1];
        a2 += v * Wc[k * 4 + 2];
        a3 += v * Wc[k * 4 + 3];
    }
#pragma unroll
    for (int o = 16; o > 0; o >>= 1) {
        a0 += __shfl_down_sync(0xffffffffu, a0, o);
        a1 += __shfl_down_sync(0xffffffffu, a1, o);
        a2 += __shfl_down_sync(0xffffffffu, a2, o);
        a3 += __shfl_down_sync(0xffffffffu, a3, o);
    }
    if (lane == 0) {
        out[(size_t)warp * 4 + 0] = a0 + bc[0];
        out[(size_t)warp * 4 + 1] = a1 + bc[1];
        out[(size_t)warp * 4 + 2] = a2 + bc[2];
        out[(size_t)warp * 4 + 3] = a3 + bc[3];
    }
}

// ---------------- host launch ----------------------------------------------
static inline void* sym(const void* s) {
    void* p = nullptr;
    cudaGetSymbolAddress(&p, s);
    return p;
}

extern "C" void kernel_launch(void* const* d_in, const int* in_sizes, int n_in,
                              void* d_out, int out_size) {
    const float* x  = (const float*)d_in[0];
    const unsigned int* e = (const unsigned int*)d_in[1];
    const float* W1 = (const float*)d_in[2];  const float* b1 = (const float*)d_in[3];
    const float* W2 = (const float*)d_in[4];  const float* b2 = (const float*)d_in[5];
    const float* W3 = (const float*)d_in[6];  const float* b3 = (const float*)d_in[7];
    const float* W4 = (const float*)d_in[8];  const float* b4 = (const float*)d_in[9];
    const float* Wc = (const float*)d_in[10]; const float* bc = (const float*)d_in[11];
    const float* g1 = (const float*)d_in[12]; const float* be1 = (const float*)d_in[13];
    const float* g2 = (const float*)d_in[14]; const float* be2 = (const float*)d_in[15];
    const float* g3 = (const float*)d_in[16]; const float* be3 = (const float*)d_in[17];
    const float* g4 = (const float*)d_in[18]; const float* be4 = (const float*)d_in[19];

    long long E = (long long)in_sizes[1] / 2;

    float* out        = (float*)d_out;
    float* out_logits = out;
    float* out_conv   = out + (size_t)NN * 4;
    float* out_bn     = out_conv + (size_t)NN * 128;

    float* xw   = (float*)sym(g_xw);
    float* h1   = (float*)sym(g_h1);
    float* h2   = (float*)sym(g_h2);
    float* h4in = (float*)sym(g_h4in);
    float* h4   = (float*)sym(g_h4);
    __nv_bfloat16* whi = (__nv_bfloat16*)sym(g_whi);
    __nv_bfloat16* wlo = (__nv_bfloat16*)sym(g_wlo);

    // ---- weight transpose + split ----
    wsplit_k<<<(512 * 256 + 255) / 256, 256>>>(W1, 512, 256, 0);
    wsplit_k<<<(256 * 512 + 255) / 256, 256>>>(W2, 256, 512, 131072);
    wsplit_k<<<(512 * 256 + 255) / 256, 256>>>(W3, 512, 256, 262144);
    wsplit_k<<<(256 * 128 + 255) / 256, 256>>>(W4, 256, 128, 393216);

    // ---- CSR build ----
    detect_k<<<1, 256>>>(e);
    zero_deg_k<<<(NN + 255) / 256, 256>>>();
    hist_k<<<(unsigned)((E + 255) / 256), 256>>>(e, E);
    dinv_k<<<(NN + 255) / 256, 256>>>();
    scan1_k<<<NB, SCAN_B>>>();
    scan2_k<<<1, 32>>>();
    scan3_k<<<(NN + 255) / 256, 256>>>();
    fill_k<<<(unsigned)((E + 255) / 256), 256>>>(e, E);

    int mgrid = (NN + 127) / 128;   // 391
    unsigned agg_blocks = (NN * 32 + 255) / 256;

    // ---- layer 1: x[.,512] @ W1[512,256] ----
    gemm_bf16x2_k<<<dim3(2, mgrid), 256>>>(x, whi, wlo, xw, NN, 256, 512);
    agg_ln_elu_k<256><<<agg_blocks, 256>>>(xw, b1, g1, be1, h1, nullptr, nullptr, nullptr);

    // ---- layer 2: h1[.,256] @ W2[256,512] ----
    gemm_bf16x2_k<<<dim3(4, mgrid), 256>>>(h1, whi + 131072, wlo + 131072,
                                           xw, NN, 512, 256);
    agg_ln_elu_k<512><<<agg_blocks, 256>>>(xw, b2, g2, be2, h2, nullptr, nullptr, nullptr);

    // ---- layer 3: h2[.,512] @ W3[512,256]; fused residual + h1 ----
    gemm_bf16x2_k<<<dim3(2, mgrid), 256>>>(h2, whi + 262144, wlo + 262144,
                                           xw, NN, 256, 512);
    agg_ln_elu_k<256><<<agg_blocks, 256>>>(xw, b3, g3, be3, h4in, h1, nullptr, nullptr);

    // ---- layer 4: h4in[.,256] @ W4[256,128]; taps out_conv/out_bn ----
    gemm_bf16x2_k<<<dim3(1, mgrid), 256>>>(h4in, whi + 393216, wlo + 393216,
                                           xw, NN, 128, 256);
    agg_ln_elu_k<128><<<agg_blocks, 256>>>(xw, b4, g4, be4, h4, nullptr, out_conv, out_bn);

    // ---- classifier ----
    classifier_k<<<(NN * 32 + 127) / 128, 128>>>(h4, Wc, bc, out_logits);
}

// round 6
// speedup vs baseline: 2.1544x; 1.1242x over previous
#include <cuda_runtime.h>
#include <cuda_bf16.h>
#include <cstdint>

#define NN 50000
#define EMAX 1700000
#define SCAN_B 512
#define NB ((NN + SCAN_B - 1) / SCAN_B)   // 98

// ---------------- scratch (device globals; no allocation allowed) ----------
__device__ float g_xw[(size_t)NN * 512];
__device__ float g_h1[(size_t)NN * 256];
__device__ float g_h2[(size_t)NN * 512];
__device__ float g_h4in[(size_t)NN * 256];   // also L2 agg tmp
__device__ float g_h4[(size_t)NN * 128];
__device__ float g_dinv[NN];
__device__ int   g_degi[NN];
__device__ int   g_off[NN];
__device__ int   g_cur[NN];
__device__ int   g_bsum[NB];
__device__ int   g_btop[NB];
__device__ int   g_csr[EMAX];
__device__ float g_nrm[EMAX];
__device__ int   g_is64;
__device__ __nv_bfloat16 g_whi[425984];
__device__ __nv_bfloat16 g_wlo[425984];

// ---------------- helpers ---------------------------------------------------
__device__ __forceinline__ uint32_t pack_bf16(float a, float b) {
    __nv_bfloat162 v = __floats2bfloat162_rn(a, b);
    return *reinterpret_cast<uint32_t*>(&v);
}
__device__ __forceinline__ void split_bf16(float a, float& hi, float& lo) {
    __nv_bfloat16 h = __float2bfloat16_rn(a);
    hi = __bfloat162float(h);
    lo = a - hi;
}
__device__ __forceinline__ void mma_bf16(float* c, uint32_t a0, uint32_t a1,
                                         uint32_t a2, uint32_t a3,
                                         uint32_t b0, uint32_t b1) {
    asm volatile(
        "mma.sync.aligned.m16n8k16.row.col.f32.bf16.bf16.f32 "
        "{%0,%1,%2,%3}, {%4,%5,%6,%7}, {%8,%9}, {%0,%1,%2,%3};\n"
        : "+f"(c[0]), "+f"(c[1]), "+f"(c[2]), "+f"(c[3])
        : "r"(a0), "r"(a1), "r"(a2), "r"(a3), "r"(b0), "r"(b1));
}

// ---------------- edge-format detect ---------------------------------------
__global__ void detect_k(const unsigned int* __restrict__ e) {
    __shared__ int ok;
    if (threadIdx.x == 0) ok = 1;
    __syncthreads();
    for (int i = threadIdx.x; i < 512; i += blockDim.x)
        if (e[2 * i + 1] != 0u) ok = 0;
    __syncthreads();
    if (threadIdx.x == 0) g_is64 = ok;
}

__device__ __forceinline__ void edge_sd(const unsigned int* e, long long E,
                                        long long i, int& s, int& d) {
    if (g_is64) { s = (int)e[2 * i]; d = (int)e[2 * (E + i)]; }
    else        { s = (int)e[i];     d = (int)e[E + i]; }
}

// ---------------- CSR build -------------------------------------------------
__global__ void zero_deg_k() {
    int i = blockIdx.x * blockDim.x + threadIdx.x;
    if (i < NN) g_degi[i] = 0;
}
__global__ void hist_k(const unsigned int* __restrict__ e, long long E) {
    long long i = (long long)blockIdx.x * blockDim.x + threadIdx.x;
    if (i >= E) return;
    int d = g_is64 ? (int)e[2 * (E + i)] : (int)e[E + i];
    atomicAdd(&g_degi[d], 1);
}
__global__ void dinv_k() {
    int i = blockIdx.x * blockDim.x + threadIdx.x;
    if (i < NN) g_dinv[i] = rsqrtf((float)g_degi[i] + 1.0f);
}
__global__ void scan1_k() {
    __shared__ int sh[SCAN_B];
    int i = blockIdx.x * SCAN_B + threadIdx.x;
    int v = (i < NN) ? g_degi[i] : 0;
    sh[threadIdx.x] = v;
    __syncthreads();
#pragma unroll
    for (int o = 1; o < SCAN_B; o <<= 1) {
        int t = (threadIdx.x >= o) ? sh[threadIdx.x - o] : 0;
        __syncthreads();
        sh[threadIdx.x] += t;
        __syncthreads();
    }
    if (i < NN) g_off[i] = sh[threadIdx.x] - v;
    if (threadIdx.x == SCAN_B - 1) g_bsum[blockIdx.x] = sh[SCAN_B - 1];
}
__global__ void scan2_k() {
    if (threadIdx.x == 0) {
        int acc = 0;
        for (int b = 0; b < NB; b++) { int t = g_bsum[b]; g_btop[b] = acc; acc += t; }
    }
}
__global__ void scan3_k() {
    int i = blockIdx.x * blockDim.x + threadIdx.x;
    if (i < NN) {
        int o = g_off[i] + g_btop[i / SCAN_B];
        g_off[i] = o;
        g_cur[i] = o;
    }
}
__global__ void fill_k(const unsigned int* __restrict__ e, long long E) {
    long long i = (long long)blockIdx.x * blockDim.x + threadIdx.x;
    if (i >= E) return;
    int s, d;
    edge_sd(e, E, i, s, d);
    int pos = atomicAdd(&g_cur[d], 1);
    g_csr[pos] = s;
    g_nrm[pos] = g_dinv[s] * g_dinv[d];
}

// ---------------- weight transpose + bf16 split -----------------------------
__global__ void wsplit_k(const float* __restrict__ W, int Kd, int Nd, int off) {
    int i = blockIdx.x * blockDim.x + threadIdx.x;
    if (i >= Kd * Nd) return;
    int k = i / Nd, n = i - k * Nd;
    float a = W[i];
    float hi, lo;
    split_bf16(a, hi, lo);
    g_whi[off + (size_t)n * Kd + k] = __float2bfloat16_rn(hi);
    g_wlo[off + (size_t)n * Kd + k] = __float2bfloat16_rn(lo);
}

// ---------------- 3xBF16 tensor-core GEMM (unchanged from R5) ---------------
__global__ __launch_bounds__(256, 1) void gemm_bf16x2_k(
    const float* __restrict__ A,
    const __nv_bfloat16* __restrict__ Bhi, const __nv_bfloat16* __restrict__ Blo,
    float* __restrict__ C, int M, int Nn, int K)
{
    __shared__ uint32_t Apk[2][2048];
    __shared__ uint32_t Bpk[2][2048];

    int tid = threadIdx.x;
    int lane = tid & 31;
    int warp = tid >> 5;
    int g = lane >> 2;
    int t = lane & 3;
    int wm = warp & 1;
    int wn = warp >> 1;
    int rowBase = blockIdx.y * 128;
    int colBase = blockIdx.x * 128;

    float acc[4][4][4];
#pragma unroll
    for (int i = 0; i < 4; i++)
#pragma unroll
        for (int j = 0; j < 4; j++)
#pragma unroll
            for (int q = 0; q < 4; q++) acc[i][j][q] = 0.0f;

    float4 stA[4];
    uint4  stB[2][2];

    auto ldg = [&](int k0) {
#pragma unroll
        for (int i = 0; i < 4; i++) {
            int idx = tid + i * 256;
            int row = idx >> 3, c4 = idx & 7;
            int gr = rowBase + row;
            stA[i] = (gr < M) ? *(const float4*)&A[(size_t)gr * K + k0 + c4 * 4]
                              : make_float4(0.f, 0.f, 0.f, 0.f);
        }
#pragma unroll
        for (int i = 0; i < 2; i++) {
            int idx = tid + i * 256;
            int n = idx >> 2, w4 = idx & 3;
            size_t go = (size_t)(colBase + n) * K + k0 + w4 * 8;
            stB[0][i] = *(const uint4*)&Bhi[go];
            stB[1][i] = *(const uint4*)&Blo[go];
        }
    };
    auto sts = [&]() {
#pragma unroll
        for (int i = 0; i < 4; i++) {
            int idx = tid + i * 256;
            int row = idx >> 3, c4 = idx & 7;
            int c = c4 * 4;
            int mt = row >> 4, rr = row & 15;
            int gg = rr & 7, h = rr >> 3;
            int ks = c >> 4, kk = c & 15;
            int khalf = kk >> 3;
            int t0 = (kk & 7) >> 1;
            int reg = h + 2 * khalf;
            int base = ((ks * 8 + mt) * 8 + gg) * 16 + reg;
            float h0, l0, h1, l1, h2, l2, h3, l3;
            split_bf16(stA[i].x, h0, l0); split_bf16(stA[i].y, h1, l1);
            split_bf16(stA[i].z, h2, l2); split_bf16(stA[i].w, h3, l3);
            Apk[0][base + t0 * 4]       = pack_bf16(h0, h1);
            Apk[0][base + (t0 + 1) * 4] = pack_bf16(h2, h3);
            Apk[1][base + t0 * 4]       = pack_bf16(l0, l1);
            Apk[1][base + (t0 + 1) * 4] = pack_bf16(l2, l3);
        }
#pragma unroll
        for (int i = 0; i < 2; i++) {
            int idx = tid + i * 256;
            int n = idx >> 2, w4 = idx & 3;
            int nt = n >> 3, gg = n & 7;
#pragma unroll
            for (int p = 0; p < 2; p++) {
                const uint32_t* w = (const uint32_t*)&stB[p][i];
#pragma unroll
                for (int wd = 0; wd < 4; wd++) {
                    int k = w4 * 8 + 2 * wd;
                    int ks = k >> 4, kk = k & 15;
                    int tt = (kk >> 1) & 3, reg = kk >> 3;
                    Bpk[p][((nt * 8 + gg) * 4 + tt) * 4 + ks * 2 + reg] = w[wd];
                }
            }
        }
    };

    ldg(0);
    for (int k0 = 0; k0 < K; k0 += 32) {
        sts();
        __syncthreads();
        if (k0 + 32 < K) ldg(k0 + 32);

        uint4 bh[4], bl[4];
#pragma unroll
        for (int j = 0; j < 4; j++) {
            int o = (((wn * 4 + j) * 8 + g) * 4 + t) * 4;
            bh[j] = *(uint4*)&Bpk[0][o];
            bl[j] = *(uint4*)&Bpk[1][o];
        }
#pragma unroll
        for (int ks = 0; ks < 2; ks++) {
            uint4 ah[4];
#pragma unroll
            for (int i = 0; i < 4; i++)
                ah[i] = *(uint4*)&Apk[0][((ks * 8 + wm * 4 + i) * 8 + g) * 16 + t * 4];
#pragma unroll
            for (int i = 0; i < 4; i++)
#pragma unroll
                for (int j = 0; j < 4; j++) {
                    uint32_t b0 = ks ? bh[j].z : bh[j].x;
                    uint32_t b1 = ks ? bh[j].w : bh[j].y;
                    mma_bf16(acc[i][j], ah[i].x, ah[i].y, ah[i].z, ah[i].w, b0, b1);
                }
#pragma unroll
            for (int i = 0; i < 4; i++)
#pragma unroll
                for (int j = 0; j < 4; j++) {
                    uint32_t b0 = ks ? bl[j].z : bl[j].x;
                    uint32_t b1 = ks ? bl[j].w : bl[j].y;
                    mma_bf16(acc[i][j], ah[i].x, ah[i].y, ah[i].z, ah[i].w, b0, b1);
                }
            uint4 al[4];
#pragma unroll
            for (int i = 0; i < 4; i++)
                al[i] = *(uint4*)&Apk[1][((ks * 8 + wm * 4 + i) * 8 + g) * 16 + t * 4];
#pragma unroll
            for (int i = 0; i < 4; i++)
#pragma unroll
                for (int j = 0; j < 4; j++) {
                    uint32_t b0 = ks ? bh[j].z : bh[j].x;
                    uint32_t b1 = ks ? bh[j].w : bh[j].y;
                    mma_bf16(acc[i][j], al[i].x, al[i].y, al[i].z, al[i].w, b0, b1);
                }
        }
        __syncthreads();
    }

#pragma unroll
    for (int i = 0; i < 4; i++) {
        int r0 = rowBase + wm * 64 + i * 16 + g;
        int r1 = r0 + 8;
#pragma unroll
        for (int j = 0; j < 4; j++) {
            int col = colBase + wn * 32 + j * 8 + t * 2;
            if (r0 < M) *(float2*)&C[(size_t)r0 * Nn + col] =
                make_float2(acc[i][j][0], acc[i][j][1]);
            if (r1 < M) *(float2*)&C[(size_t)r1 * Nn + col] =
                make_float2(acc[i][j][2], acc[i][j][3]);
        }
    }
}

// ---------------- fused warp-per-node: CSR gather + self + bias + LN + ELU --
template<int F>
__global__ __launch_bounds__(256) void agg_ln_elu_k(
    const float* __restrict__ xw,
    const float* __restrict__ bias,
    const float* __restrict__ gamma,
    const float* __restrict__ beta,
    float* __restrict__ out,
    const float* __restrict__ resid,
    float* __restrict__ out_raw,
    float* __restrict__ out_bn)
{
    constexpr int RF = F / 128;
    int warp = (blockIdx.x * blockDim.x + threadIdx.x) >> 5;
    int lane = threadIdx.x & 31;
    if (warp >= NN) return;
    int d = warp;

    float4 acc[RF];
#pragma unroll
    for (int i = 0; i < RF; i++) acc[i] = make_float4(0.f, 0.f, 0.f, 0.f);

    int beg = g_off[d];
    int cnt = g_degi[d];

    for (int b0 = 0; b0 < cnt; b0 += 32) {
        int n = min(32, cnt - b0);
        int   s_l = 0;
        float n_l = 0.f;
        if (lane < n) {
            s_l = g_csr[beg + b0 + lane];
            n_l = g_nrm[beg + b0 + lane];
        }
        for (int j = 0; j < n; j++) {
            int   s   = __shfl_sync(0xffffffffu, s_l, j);
            float nrm = __shfl_sync(0xffffffffu, n_l, j);
            const float4* row = (const float4*)(xw + (size_t)s * F);
#pragma unroll
            for (int i = 0; i < RF; i++) {
                float4 v = row[i * 32 + lane];
                acc[i].x = fmaf(nrm, v.x, acc[i].x);
                acc[i].y = fmaf(nrm, v.y, acc[i].y);
                acc[i].z = fmaf(nrm, v.z, acc[i].z);
                acc[i].w = fmaf(nrm, v.w, acc[i].w);
            }
        }
    }

    {
        float dd = g_dinv[d];
        float nrm = dd * dd;
        const float4* row = (const float4*)(xw + (size_t)d * F);
        const float4* bb  = (const float4*)bias;
#pragma unroll
        for (int i = 0; i < RF; i++) {
            float4 v = row[i * 32 + lane];
            float4 b = bb[i * 32 + lane];
            acc[i].x = fmaf(nrm, v.x, acc[i].x) + b.x;
            acc[i].y = fmaf(nrm, v.y, acc[i].y) + b.y;
            acc[i].z = fmaf(nrm, v.z, acc[i].z) + b.z;
            acc[i].w = fmaf(nrm, v.w, acc[i].w) + b.w;
        }
    }

    float s = 0.f, q = 0.f;
#pragma unroll
    for (int i = 0; i < RF; i++) {
        s += acc[i].x + acc[i].y + acc[i].z + acc[i].w;
        q += acc[i].x * acc[i].x + acc[i].y * acc[i].y
           + acc[i].z * acc[i].z + acc[i].w * acc[i].w;
    }
#pragma unroll
    for (int o = 16; o > 0; o >>= 1) {
        s += __shfl_xor_sync(0xffffffffu, s, o);
        q += __shfl_xor_sync(0xffffffffu, q, o);
    }
    constexpr float invF = 1.0f / F;
    float mu = s * invF;
    float var = q * invF - mu * mu;
    float rstd = rsqrtf(var + 1e-5f);

    const float4* gp = (const float4*)gamma;
    const float4* bp = (const float4*)beta;
    float4* op = (float4*)(out + (size_t)d * F);
    const float4* rp = resid ? (const float4*)(resid + (size_t)d * F) : nullptr;
    float4* rawp = out_raw ? (float4*)(out_raw + (size_t)d * F) : nullptr;
    float4* bnp  = out_bn  ? (float4*)(out_bn  + (size_t)d * F) : nullptr;

#pragma unroll
    for (int i = 0; i < RF; i++) {
        int idx = i * 32 + lane;
        float4 gv = gp[idx];
        float4 bv = bp[idx];
        float4 y;
        y.x = (acc[i].x - mu) * rstd * gv.x + bv.x;
        y.y = (acc[i].y - mu) * rstd * gv.y + bv.y;
        y.z = (acc[i].z - mu) * rstd * gv.z + bv.z;
        y.w = (acc[i].w - mu) * rstd * gv.w + bv.w;
        if (rawp) rawp[idx] = acc[i];
        if (bnp)  bnp[idx]  = y;
        float4 eo;
        eo.x = y.x > 0.f ? y.x : expm1f(y.x);
        eo.y = y.y > 0.f ? y.y : expm1f(y.y);
        eo.z = y.z > 0.f ? y.z : expm1f(y.z);
        eo.w = y.w > 0.f ? y.w : expm1f(y.w);
        if (rp) {
            float4 r = rp[idx];
            eo.x += r.x; eo.y += r.y; eo.z += r.z; eo.w += r.w;
        }
        op[idx] = eo;
    }
}

// ---------------- gather-only aggregation (self-loop, no bias/LN) -----------
template<int F>
__global__ __launch_bounds__(256) void agg_only_k(
    const float* __restrict__ in, float* __restrict__ out)
{
    constexpr int RF = F / 128;
    int warp = (blockIdx.x * blockDim.x + threadIdx.x) >> 5;
    int lane = threadIdx.x & 31;
    if (warp >= NN) return;
    int d = warp;

    float4 acc[RF];
#pragma unroll
    for (int i = 0; i < RF; i++) acc[i] = make_float4(0.f, 0.f, 0.f, 0.f);

    int beg = g_off[d];
    int cnt = g_degi[d];

    for (int b0 = 0; b0 < cnt; b0 += 32) {
        int n = min(32, cnt - b0);
        int   s_l = 0;
        float n_l = 0.f;
        if (lane < n) {
            s_l = g_csr[beg + b0 + lane];
            n_l = g_nrm[beg + b0 + lane];
        }
        for (int j = 0; j < n; j++) {
            int   s   = __shfl_sync(0xffffffffu, s_l, j);
            float nrm = __shfl_sync(0xffffffffu, n_l, j);
            const float4* row = (const float4*)(in + (size_t)s * F);
#pragma unroll
            for (int i = 0; i < RF; i++) {
                float4 v = row[i * 32 + lane];
                acc[i].x = fmaf(nrm, v.x, acc[i].x);
                acc[i].y = fmaf(nrm, v.y, acc[i].y);
                acc[i].z = fmaf(nrm, v.z, acc[i].z);
                acc[i].w = fmaf(nrm, v.w, acc[i].w);
            }
        }
    }

    {
        float dd = g_dinv[d];
        float nrm = dd * dd;
        const float4* row = (const float4*)(in + (size_t)d * F);
#pragma unroll
        for (int i = 0; i < RF; i++) {
            float4 v = row[i * 32 + lane];
            acc[i].x = fmaf(nrm, v.x, acc[i].x);
            acc[i].y = fmaf(nrm, v.y, acc[i].y);
            acc[i].z = fmaf(nrm, v.z, acc[i].z);
            acc[i].w = fmaf(nrm, v.w, acc[i].w);
        }
    }

    float4* op = (float4*)(out + (size_t)d * F);
#pragma unroll
    for (int i = 0; i < RF; i++) op[i * 32 + lane] = acc[i];
}

// ---------------- standalone bias + LN + ELU (block per node) ---------------
template<int F>
__global__ void ln_elu_k(const float* __restrict__ in,
                         const float* __restrict__ bias,
                         const float* __restrict__ gamma,
                         const float* __restrict__ beta,
                         float* __restrict__ out)
{
    int node = blockIdx.x;
    int tid = threadIdx.x;
    constexpr int NT = F / 4;
    constexpr int NW = NT / 32;
    const float4* row = (const float4*)(in + (size_t)node * F);
    float4 v = row[tid];
    float4 bb = ((const float4*)bias)[tid];
    v.x += bb.x; v.y += bb.y; v.z += bb.z; v.w += bb.w;
    float s = v.x + v.y + v.z + v.w;
    float q = v.x * v.x + v.y * v.y + v.z * v.z + v.w * v.w;
#pragma unroll
    for (int o = 16; o > 0; o >>= 1) {
        s += __shfl_xor_sync(0xffffffffu, s, o);
        q += __shfl_xor_sync(0xffffffffu, q, o);
    }
    __shared__ float ss[NW], sq[NW];
    int wid = tid >> 5, lane = tid & 31;
    if (NW > 1) {
        if (lane == 0) { ss[wid] = s; sq[wid] = q; }
        __syncthreads();
        s = 0.f; q = 0.f;
#pragma unroll
        for (int w = 0; w < NW; w++) { s += ss[w]; q += sq[w]; }
    }
    constexpr float invF = 1.0f / F;
    float mu = s * invF;
    float var = q * invF - mu * mu;
    float rstd = rsqrtf(var + 1e-5f);
    float4 gv = ((const float4*)gamma)[tid];
    float4 bv = ((const float4*)beta)[tid];
    float4 y;
    y.x = (v.x - mu) * rstd * gv.x + bv.x;
    y.y = (v.y - mu) * rstd * gv.y + bv.y;
    y.z = (v.z - mu) * rstd * gv.z + bv.z;
    y.w = (v.w - mu) * rstd * gv.w + bv.w;
    float4 eo;
    eo.x = y.x > 0.f ? y.x : expm1f(y.x);
    eo.y = y.y > 0.f ? y.y : expm1f(y.y);
    eo.z = y.z > 0.f ? y.z : expm1f(y.z);
    eo.w = y.w > 0.f ? y.w : expm1f(y.w);
    ((float4*)(out + (size_t)node * F))[tid] = eo;
}

// ---------------- classifier: [N,128] @ [128,4] + bc -----------------------
__global__ void classifier_k(const float* __restrict__ h,
                             const float* __restrict__ Wc,
                             const float* __restrict__ bc,
                             float* __restrict__ out) {
    int warp = (blockIdx.x * blockDim.x + threadIdx.x) >> 5;
    int lane = threadIdx.x & 31;
    if (warp >= NN) return;
    const float* row = h + (size_t)warp * 128;
    float a0 = 0.f, a1 = 0.f, a2 = 0.f, a3 = 0.f;
    for (int k = lane; k < 128; k += 32) {
        float v = row[k];
        a0 += v * Wc[k * 4 + 0];
        a1 += v * Wc[k * 4 + 1];
        a2 += v * Wc[k * 4 + 2];
        a3 += v * Wc[k * 4 + 3];
    }
#pragma unroll
    for (int o = 16; o > 0; o >>= 1) {
        a0 += __shfl_down_sync(0xffffffffu, a0, o);
        a1 += __shfl_down_sync(0xffffffffu, a1, o);
        a2 += __shfl_down_sync(0xffffffffu, a2, o);
        a3 += __shfl_down_sync(0xffffffffu, a3, o);
    }
    if (lane == 0) {
        out[(size_t)warp * 4 + 0] = a0 + bc[0];
        out[(size_t)warp * 4 + 1] = a1 + bc[1];
        out[(size_t)warp * 4 + 2] = a2 + bc[2];
        out[(size_t)warp * 4 + 3] = a3 + bc[3];
    }
}

// ---------------- host launch ----------------------------------------------
static inline void* sym(const void* s) {
    void* p = nullptr;
    cudaGetSymbolAddress(&p, s);
    return p;
}

extern "C" void kernel_launch(void* const* d_in, const int* in_sizes, int n_in,
                              void* d_out, int out_size) {
    const float* x  = (const float*)d_in[0];
    const unsigned int* e = (const unsigned int*)d_in[1];
    const float* W1 = (const float*)d_in[2];  const float* b1 = (const float*)d_in[3];
    const float* W2 = (const float*)d_in[4];  const float* b2 = (const float*)d_in[5];
    const float* W3 = (const float*)d_in[6];  const float* b3 = (const float*)d_in[7];
    const float* W4 = (const float*)d_in[8];  const float* b4 = (const float*)d_in[9];
    const float* Wc = (const float*)d_in[10]; const float* bc = (const float*)d_in[11];
    const float* g1 = (const float*)d_in[12]; const float* be1 = (const float*)d_in[13];
    const float* g2 = (const float*)d_in[14]; const float* be2 = (const float*)d_in[15];
    const float* g3 = (const float*)d_in[16]; const float* be3 = (const float*)d_in[17];
    const float* g4 = (const float*)d_in[18]; const float* be4 = (const float*)d_in[19];

    long long E = (long long)in_sizes[1] / 2;

    float* out        = (float*)d_out;
    float* out_logits = out;
    float* out_conv   = out + (size_t)NN * 4;
    float* out_bn     = out_conv + (size_t)NN * 128;

    float* xw   = (float*)sym(g_xw);
    float* h1   = (float*)sym(g_h1);
    float* h2   = (float*)sym(g_h2);
    float* h4in = (float*)sym(g_h4in);   // doubles as L2 agg tmp
    float* h4   = (float*)sym(g_h4);
    __nv_bfloat16* whi = (__nv_bfloat16*)sym(g_whi);
    __nv_bfloat16* wlo = (__nv_bfloat16*)sym(g_wlo);

    // side stream + events (created once; resources, not work)
    static cudaStream_t s2 = nullptr;
    static cudaEvent_t ev1 = nullptr, ev2 = nullptr;
    if (s2 == nullptr) {
        cudaStreamCreateWithFlags(&s2, cudaStreamNonBlocking);
        cudaEventCreateWithFlags(&ev1, cudaEventDisableTiming);
        cudaEventCreateWithFlags(&ev2, cudaEventDisableTiming);
    }

    int mgrid = (NN + 127) / 128;   // 391
    unsigned agg_blocks = (NN * 32 + 255) / 256;

    // ---- fork: CSR build + W2..W4 split on s2, overlapped with L1 GEMM ----
    cudaEventRecord(ev1, 0);
    cudaStreamWaitEvent(s2, ev1, 0);

    detect_k<<<1, 256, 0, s2>>>(e);
    zero_deg_k<<<(NN + 255) / 256, 256, 0, s2>>>();
    hist_k<<<(unsigned)((E + 255) / 256), 256, 0, s2>>>(e, E);
    dinv_k<<<(NN + 255) / 256, 256, 0, s2>>>();
    scan1_k<<<NB, SCAN_B, 0, s2>>>();
    scan2_k<<<1, 32, 0, s2>>>();
    scan3_k<<<(NN + 255) / 256, 256, 0, s2>>>();
    fill_k<<<(unsigned)((E + 255) / 256), 256, 0, s2>>>(e, E);
    wsplit_k<<<(256 * 512 + 255) / 256, 256, 0, s2>>>(W2, 256, 512, 131072);
    wsplit_k<<<(512 * 256 + 255) / 256, 256, 0, s2>>>(W3, 512, 256, 262144);
    wsplit_k<<<(256 * 128 + 255) / 256, 256, 0, s2>>>(W4, 256, 128, 393216);
    cudaEventRecord(ev2, s2);

    // main stream: W1 split + layer-1 GEMM run concurrently with s2
    wsplit_k<<<(512 * 256 + 255) / 256, 256>>>(W1, 512, 256, 0);
    gemm_bf16x2_k<<<dim3(2, mgrid), 256>>>(x, whi, wlo, xw, NN, 256, 512);

    // join before first aggregation
    cudaStreamWaitEvent(0, ev2, 0);

    // ---- layer 1 epilogue: agg + LN + ELU -> h1 ----
    agg_ln_elu_k<256><<<agg_blocks, 256>>>(xw, b1, g1, be1, h1, nullptr, nullptr, nullptr);

    // ---- layer 2 (agg-first): tmp = A_hat h1; gemm tmp@W2; LN+ELU -> h2 ----
    agg_only_k<256><<<agg_blocks, 256>>>(h1, h4in);
    gemm_bf16x2_k<<<dim3(4, mgrid), 256>>>(h4in, whi + 131072, wlo + 131072,
                                           xw, NN, 512, 256);
    ln_elu_k<512><<<NN, 128>>>(xw, b2, g2, be2, h2);

    // ---- layer 3: gemm(h2)@W3; agg + LN + ELU + residual(h1) -> h4in ----
    gemm_bf16x2_k<<<dim3(2, mgrid), 256>>>(h2, whi + 262144, wlo + 262144,
                                           xw, NN, 256, 512);
    agg_ln_elu_k<256><<<agg_blocks, 256>>>(xw, b3, g3, be3, h4in, h1, nullptr, nullptr);

    // ---- layer 4: gemm(h4in)@W4; agg + LN + ELU, taps out_conv/out_bn ----
    gemm_bf16x2_k<<<dim3(1, mgrid), 256>>>(h4in, whi + 393216, wlo + 393216,
                                           xw, NN, 128, 256);
    agg_ln_elu_k<128><<<agg_blocks, 256>>>(xw, b4, g4, be4, h4, nullptr, out_conv, out_bn);

    // ---- classifier ----
    classifier_k<<<(NN * 32 + 127) / 128, 128>>>(h4, Wc, bc, out_logits);
}

// round 7
// speedup vs baseline: 2.2161x; 1.0286x over previous
#include <cuda_runtime.h>
#include <cuda_bf16.h>
#include <cstdint>

#define NN 50000
#define EMAX 1700000
#define SCAN_B 512
#define NB ((NN + SCAN_B - 1) / SCAN_B)   // 98

// ---------------- scratch (device globals; no allocation allowed) ----------
__device__ float g_xw[(size_t)NN * 512];
__device__ float g_h1[(size_t)NN * 256];
__device__ float g_h2[(size_t)NN * 512];
__device__ float g_h4in[(size_t)NN * 256];   // also L2 agg tmp
__device__ float g_dinv[NN];
__device__ int   g_degi[NN];
__device__ int   g_off[NN];
__device__ int   g_cur[NN];
__device__ int   g_bsum[NB];
__device__ int   g_btop[NB];
__device__ int   g_csr[EMAX];
__device__ float g_nrm[EMAX];
__device__ int   g_is64;
__device__ __nv_bfloat16 g_whi[425984];
__device__ __nv_bfloat16 g_wlo[425984];

// ---------------- helpers ---------------------------------------------------
__device__ __forceinline__ uint32_t pack_bf16(float a, float b) {
    __nv_bfloat162 v = __floats2bfloat162_rn(a, b);
    return *reinterpret_cast<uint32_t*>(&v);
}
__device__ __forceinline__ void split_bf16(float a, float& hi, float& lo) {
    __nv_bfloat16 h = __float2bfloat16_rn(a);
    hi = __bfloat162float(h);
    lo = a - hi;
}
__device__ __forceinline__ void mma_bf16(float* c, uint32_t a0, uint32_t a1,
                                         uint32_t a2, uint32_t a3,
                                         uint32_t b0, uint32_t b1) {
    asm volatile(
        "mma.sync.aligned.m16n8k16.row.col.f32.bf16.bf16.f32 "
        "{%0,%1,%2,%3}, {%4,%5,%6,%7}, {%8,%9}, {%0,%1,%2,%3};\n"
        : "+f"(c[0]), "+f"(c[1]), "+f"(c[2]), "+f"(c[3])
        : "r"(a0), "r"(a1), "r"(a2), "r"(a3), "r"(b0), "r"(b1));
}

// ---------------- edge-format detect ---------------------------------------
__global__ void detect_k(const unsigned int* __restrict__ e) {
    __shared__ int ok;
    if (threadIdx.x == 0) ok = 1;
    __syncthreads();
    for (int i = threadIdx.x; i < 512; i += blockDim.x)
        if (e[2 * i + 1] != 0u) ok = 0;
    __syncthreads();
    if (threadIdx.x == 0) g_is64 = ok;
}

__device__ __forceinline__ void edge_sd(const unsigned int* e, long long E,
                                        long long i, int& s, int& d) {
    if (g_is64) { s = (int)e[2 * i]; d = (int)e[2 * (E + i)]; }
    else        { s = (int)e[i];     d = (int)e[E + i]; }
}

// ---------------- CSR build -------------------------------------------------
__global__ void zero_deg_k() {
    int i = blockIdx.x * blockDim.x + threadIdx.x;
    if (i < NN) g_degi[i] = 0;
}
__global__ void hist_k(const unsigned int* __restrict__ e, long long E) {
    long long i = (long long)blockIdx.x * blockDim.x + threadIdx.x;
    if (i >= E) return;
    int d = g_is64 ? (int)e[2 * (E + i)] : (int)e[E + i];
    atomicAdd(&g_degi[d], 1);
}
__global__ void dinv_k() {
    int i = blockIdx.x * blockDim.x + threadIdx.x;
    if (i < NN) g_dinv[i] = rsqrtf((float)g_degi[i] + 1.0f);
}
__global__ void scan1_k() {
    __shared__ int sh[SCAN_B];
    int i = blockIdx.x * SCAN_B + threadIdx.x;
    int v = (i < NN) ? g_degi[i] : 0;
    sh[threadIdx.x] = v;
    __syncthreads();
#pragma unroll
    for (int o = 1; o < SCAN_B; o <<= 1) {
        int t = (threadIdx.x >= o) ? sh[threadIdx.x - o] : 0;
        __syncthreads();
        sh[threadIdx.x] += t;
        __syncthreads();
    }
    if (i < NN) g_off[i] = sh[threadIdx.x] - v;
    if (threadIdx.x == SCAN_B - 1) g_bsum[blockIdx.x] = sh[SCAN_B - 1];
}
__global__ void scan2_k() {
    if (threadIdx.x == 0) {
        int acc = 0;
        for (int b = 0; b < NB; b++) { int t = g_bsum[b]; g_btop[b] = acc; acc += t; }
    }
}
__global__ void scan3_k() {
    int i = blockIdx.x * blockDim.x + threadIdx.x;
    if (i < NN) {
        int o = g_off[i] + g_btop[i / SCAN_B];
        g_off[i] = o;
        g_cur[i] = o;
    }
}
__global__ void fill_k(const unsigned int* __restrict__ e, long long E) {
    long long i = (long long)blockIdx.x * blockDim.x + threadIdx.x;
    if (i >= E) return;
    int s, d;
    edge_sd(e, E, i, s, d);
    int pos = atomicAdd(&g_cur[d], 1);
    g_csr[pos] = s;
    g_nrm[pos] = g_dinv[s] * g_dinv[d];
}

// ---------------- weight transpose + bf16 split -----------------------------
__global__ void wsplit_k(const float* __restrict__ W, int Kd, int Nd, int off) {
    int i = blockIdx.x * blockDim.x + threadIdx.x;
    if (i >= Kd * Nd) return;
    int k = i / Nd, n = i - k * Nd;
    float a = W[i];
    float hi, lo;
    split_bf16(a, hi, lo);
    g_whi[off + (size_t)n * Kd + k] = __float2bfloat16_rn(hi);
    g_wlo[off + (size_t)n * Kd + k] = __float2bfloat16_rn(lo);
}

// ---------------- 3xBF16 tensor-core GEMM, double-buffered ------------------
// Dynamic smem: 2 stages x (Apk 2x2048 + Bpk 2x2048) u32 = 64 KB.
__global__ __launch_bounds__(256) void gemm_bf16x2_k(
    const float* __restrict__ A,
    const __nv_bfloat16* __restrict__ Bhi, const __nv_bfloat16* __restrict__ Blo,
    float* __restrict__ C, int M, int Nn, int K)
{
    extern __shared__ uint32_t dsm[];   // [stage][A0|A1|B0|B1][2048]

    int tid = threadIdx.x;
    int lane = tid & 31;
    int warp = tid >> 5;
    int g = lane >> 2;
    int t = lane & 3;
    int wm = warp & 1;
    int wn = warp >> 1;
    int rowBase = blockIdx.y * 128;
    int colBase = blockIdx.x * 128;

    float acc[4][4][4];
#pragma unroll
    for (int i = 0; i < 4; i++)
#pragma unroll
        for (int j = 0; j < 4; j++)
#pragma unroll
            for (int q = 0; q < 4; q++) acc[i][j][q] = 0.0f;

    float4 stA[4];
    uint4  stB[2][2];

    auto ldg = [&](int k0) {
#pragma unroll
        for (int i = 0; i < 4; i++) {
            int idx = tid + i * 256;
            int row = idx >> 3, c4 = idx & 7;
            int gr = rowBase + row;
            stA[i] = (gr < M) ? *(const float4*)&A[(size_t)gr * K + k0 + c4 * 4]
                              : make_float4(0.f, 0.f, 0.f, 0.f);
        }
#pragma unroll
        for (int i = 0; i < 2; i++) {
            int idx = tid + i * 256;
            int n = idx >> 2, w4 = idx & 3;
            size_t go = (size_t)(colBase + n) * K + k0 + w4 * 8;
            stB[0][i] = *(const uint4*)&Bhi[go];
            stB[1][i] = *(const uint4*)&Blo[go];
        }
    };
    auto sts = [&](int s) {
        uint32_t* A0 = dsm + s * 8192;
        uint32_t* A1 = A0 + 2048;
        uint32_t* B0 = A0 + 4096;
        uint32_t* B1 = A0 + 6144;
#pragma unroll
        for (int i = 0; i < 4; i++) {
            int idx = tid + i * 256;
            int row = idx >> 3, c4 = idx & 7;
            int c = c4 * 4;
            int mt = row >> 4, rr = row & 15;
            int gg = rr & 7, h = rr >> 3;
            int ks = c >> 4, kk = c & 15;
            int khalf = kk >> 3;
            int t0 = (kk & 7) >> 1;
            int reg = h + 2 * khalf;
            int base = ((ks * 8 + mt) * 8 + gg) * 16 + reg;
            float h0, l0, h1, l1, h2, l2, h3, l3;
            split_bf16(stA[i].x, h0, l0); split_bf16(stA[i].y, h1, l1);
            split_bf16(stA[i].z, h2, l2); split_bf16(stA[i].w, h3, l3);
            A0[base + t0 * 4]       = pack_bf16(h0, h1);
            A0[base + (t0 + 1) * 4] = pack_bf16(h2, h3);
            A1[base + t0 * 4]       = pack_bf16(l0, l1);
            A1[base + (t0 + 1) * 4] = pack_bf16(l2, l3);
        }
#pragma unroll
        for (int i = 0; i < 2; i++) {
            int idx = tid + i * 256;
            int n = idx >> 2, w4 = idx & 3;
            int nt = n >> 3, gg = n & 7;
#pragma unroll
            for (int p = 0; p < 2; p++) {
                uint32_t* Bp = p ? B1 : B0;
                const uint32_t* w = (const uint32_t*)&stB[p][i];
#pragma unroll
                for (int wd = 0; wd < 4; wd++) {
                    int k = w4 * 8 + 2 * wd;
                    int ks = k >> 4, kk = k & 15;
                    int tt = (kk >> 1) & 3, reg = kk >> 3;
                    Bp[((nt * 8 + gg) * 4 + tt) * 4 + ks * 2 + reg] = w[wd];
                }
            }
        }
    };
    auto comp = [&](int s) {
        uint32_t* A0 = dsm + s * 8192;
        uint32_t* A1 = A0 + 2048;
        uint32_t* B0 = A0 + 4096;
        uint32_t* B1 = A0 + 6144;
        uint4 bh[4], bl[4];
#pragma unroll
        for (int j = 0; j < 4; j++) {
            int o = (((wn * 4 + j) * 8 + g) * 4 + t) * 4;
            bh[j] = *(uint4*)&B0[o];
            bl[j] = *(uint4*)&B1[o];
        }
#pragma unroll
        for (int ks = 0; ks < 2; ks++) {
            uint4 ah[4];
#pragma unroll
            for (int i = 0; i < 4; i++)
                ah[i] = *(uint4*)&A0[((ks * 8 + wm * 4 + i) * 8 + g) * 16 + t * 4];
#pragma unroll
            for (int i = 0; i < 4; i++)
#pragma unroll
                for (int j = 0; j < 4; j++) {
                    uint32_t b0 = ks ? bh[j].z : bh[j].x;
                    uint32_t b1 = ks ? bh[j].w : bh[j].y;
                    mma_bf16(acc[i][j], ah[i].x, ah[i].y, ah[i].z, ah[i].w, b0, b1);
                }
#pragma unroll
            for (int i = 0; i < 4; i++)
#pragma unroll
                for (int j = 0; j < 4; j++) {
                    uint32_t b0 = ks ? bl[j].z : bl[j].x;
                    uint32_t b1 = ks ? bl[j].w : bl[j].y;
                    mma_bf16(acc[i][j], ah[i].x, ah[i].y, ah[i].z, ah[i].w, b0, b1);
                }
            uint4 al[4];
#pragma unroll
            for (int i = 0; i < 4; i++)
                al[i] = *(uint4*)&A1[((ks * 8 + wm * 4 + i) * 8 + g) * 16 + t * 4];
#pragma unroll
            for (int i = 0; i < 4; i++)
#pragma unroll
                for (int j = 0; j < 4; j++) {
                    uint32_t b0 = ks ? bh[j].z : bh[j].x;
                    uint32_t b1 = ks ? bh[j].w : bh[j].y;
                    mma_bf16(acc[i][j], al[i].x, al[i].y, al[i].z, al[i].w, b0, b1);
                }
        }
    };

    int nch = K >> 5;
    ldg(0);
    sts(0);
    __syncthreads();
    for (int c = 0; c < nch; c++) {
        int cur = c & 1;
        if (c + 1 < nch) ldg((c + 1) << 5);
        comp(cur);
        if (c + 1 < nch) sts(cur ^ 1);
        __syncthreads();
    }

#pragma unroll
    for (int i = 0; i < 4; i++) {
        int r0 = rowBase + wm * 64 + i * 16 + g;
        int r1 = r0 + 8;
#pragma unroll
        for (int j = 0; j < 4; j++) {
            int col = colBase + wn * 32 + j * 8 + t * 2;
            if (r0 < M) *(float2*)&C[(size_t)r0 * Nn + col] =
                make_float2(acc[i][j][0], acc[i][j][1]);
            if (r1 < M) *(float2*)&C[(size_t)r1 * Nn + col] =
                make_float2(acc[i][j][2], acc[i][j][3]);
        }
    }
}

// ---------------- fused warp-per-node: CSR gather + self + bias + LN + ELU --
// Optional: residual add, raw/bn taps, and fused classifier (F==128 only).
template<int F>
__global__ __launch_bounds__(256) void agg_ln_elu_k(
    const float* __restrict__ xw,
    const float* __restrict__ bias,
    const float* __restrict__ gamma,
    const float* __restrict__ beta,
    float* __restrict__ out,
    const float* __restrict__ resid,
    float* __restrict__ out_raw,
    float* __restrict__ out_bn,
    const float* __restrict__ wc = nullptr,
    const float* __restrict__ bcp = nullptr,
    float* __restrict__ logits = nullptr)
{
    constexpr int RF = F / 128;
    int warp = (blockIdx.x * blockDim.x + threadIdx.x) >> 5;
    int lane = threadIdx.x & 31;
    if (warp >= NN) return;
    int d = warp;

    float4 acc[RF];
#pragma unroll
    for (int i = 0; i < RF; i++) acc[i] = make_float4(0.f, 0.f, 0.f, 0.f);

    int beg = g_off[d];
    int cnt = g_degi[d];

    for (int b0 = 0; b0 < cnt; b0 += 32) {
        int n = min(32, cnt - b0);
        int   s_l = 0;
        float n_l = 0.f;
        if (lane < n) {
            s_l = g_csr[beg + b0 + lane];
            n_l = g_nrm[beg + b0 + lane];
        }
        for (int j = 0; j < n; j++) {
            int   s   = __shfl_sync(0xffffffffu, s_l, j);
            float nrm = __shfl_sync(0xffffffffu, n_l, j);
            const float4* row = (const float4*)(xw + (size_t)s * F);
#pragma unroll
            for (int i = 0; i < RF; i++) {
                float4 v = row[i * 32 + lane];
                acc[i].x = fmaf(nrm, v.x, acc[i].x);
                acc[i].y = fmaf(nrm, v.y, acc[i].y);
                acc[i].z = fmaf(nrm, v.z, acc[i].z);
                acc[i].w = fmaf(nrm, v.w, acc[i].w);
            }
        }
    }

    {
        float dd = g_dinv[d];
        float nrm = dd * dd;
        const float4* row = (const float4*)(xw + (size_t)d * F);
        const float4* bb  = (const float4*)bias;
#pragma unroll
        for (int i = 0; i < RF; i++) {
            float4 v = row[i * 32 + lane];
            float4 b = bb[i * 32 + lane];
            acc[i].x = fmaf(nrm, v.x, acc[i].x) + b.x;
            acc[i].y = fmaf(nrm, v.y, acc[i].y) + b.y;
            acc[i].z = fmaf(nrm, v.z, acc[i].z) + b.z;
            acc[i].w = fmaf(nrm, v.w, acc[i].w) + b.w;
        }
    }

    float s = 0.f, q = 0.f;
#pragma unroll
    for (int i = 0; i < RF; i++) {
        s += acc[i].x + acc[i].y + acc[i].z + acc[i].w;
        q += acc[i].x * acc[i].x + acc[i].y * acc[i].y
           + acc[i].z * acc[i].z + acc[i].w * acc[i].w;
    }
#pragma unroll
    for (int o = 16; o > 0; o >>= 1) {
        s += __shfl_xor_sync(0xffffffffu, s, o);
        q += __shfl_xor_sync(0xffffffffu, q, o);
    }
    constexpr float invF = 1.0f / F;
    float mu = s * invF;
    float var = q * invF - mu * mu;
    float rstd = rsqrtf(var + 1e-5f);

    const float4* gp = (const float4*)gamma;
    const float4* bp = (const float4*)beta;
    float4* op = out ? (float4*)(out + (size_t)d * F) : nullptr;
    const float4* rp = resid ? (const float4*)(resid + (size_t)d * F) : nullptr;
    float4* rawp = out_raw ? (float4*)(out_raw + (size_t)d * F) : nullptr;
    float4* bnp  = out_bn  ? (float4*)(out_bn  + (size_t)d * F) : nullptr;

    float4 eo_last;
#pragma unroll
    for (int i = 0; i < RF; i++) {
        int idx = i * 32 + lane;
        float4 gv = gp[idx];
        float4 bv = bp[idx];
        float4 y;
        y.x = (acc[i].x - mu) * rstd * gv.x + bv.x;
        y.y = (acc[i].y - mu) * rstd * gv.y + bv.y;
        y.z = (acc[i].z - mu) * rstd * gv.z + bv.z;
        y.w = (acc[i].w - mu) * rstd * gv.w + bv.w;
        if (rawp) rawp[idx] = acc[i];
        if (bnp)  bnp[idx]  = y;
        float4 eo;
        eo.x = y.x > 0.f ? y.x : expm1f(y.x);
        eo.y = y.y > 0.f ? y.y : expm1f(y.y);
        eo.z = y.z > 0.f ? y.z : expm1f(y.z);
        eo.w = y.w > 0.f ? y.w : expm1f(y.w);
        if (rp) {
            float4 r = rp[idx];
            eo.x += r.x; eo.y += r.y; eo.z += r.z; eo.w += r.w;
        }
        if (op) op[idx] = eo;
        eo_last = eo;
    }

    // fused classifier (only for RF==1 / F==128): lane holds features 4*lane..+3
    if (RF == 1 && wc) {
        const float4* wrow = (const float4*)wc;     // [128] rows of 4 classes
        float4 w0 = wrow[lane * 4 + 0];
        float4 w1 = wrow[lane * 4 + 1];
        float4 w2 = wrow[lane * 4 + 2];
        float4 w3 = wrow[lane * 4 + 3];
        float c0 = eo_last.x * w0.x + eo_last.y * w1.x + eo_last.z * w2.x + eo_last.w * w3.x;
        float c1 = eo_last.x * w0.y + eo_last.y * w1.y + eo_last.z * w2.y + eo_last.w * w3.y;
        float c2 = eo_last.x * w0.z + eo_last.y * w1.z + eo_last.z * w2.z + eo_last.w * w3.z;
        float c3 = eo_last.x * w0.w + eo_last.y * w1.w + eo_last.z * w2.w + eo_last.w * w3.w;
#pragma unroll
        for (int o = 16; o > 0; o >>= 1) {
            c0 += __shfl_down_sync(0xffffffffu, c0, o);
            c1 += __shfl_down_sync(0xffffffffu, c1, o);
            c2 += __shfl_down_sync(0xffffffffu, c2, o);
            c3 += __shfl_down_sync(0xffffffffu, c3, o);
        }
        if (lane == 0) {
            float4 lg = make_float4(c0 + bcp[0], c1 + bcp[1],
                                    c2 + bcp[2], c3 + bcp[3]);
            *(float4*)&logits[(size_t)d * 4] = lg;
        }
    }
}

// ---------------- gather-only aggregation (self-loop, no bias/LN) -----------
template<int F>
__global__ __launch_bounds__(256) void agg_only_k(
    const float* __restrict__ in, float* __restrict__ out)
{
    constexpr int RF = F / 128;
    int warp = (blockIdx.x * blockDim.x + threadIdx.x) >> 5;
    int lane = threadIdx.x & 31;
    if (warp >= NN) return;
    int d = warp;

    float4 acc[RF];
#pragma unroll
    for (int i = 0; i < RF; i++) acc[i] = make_float4(0.f, 0.f, 0.f, 0.f);

    int beg = g_off[d];
    int cnt = g_degi[d];

    for (int b0 = 0; b0 < cnt; b0 += 32) {
        int n = min(32, cnt - b0);
        int   s_l = 0;
        float n_l = 0.f;
        if (lane < n) {
            s_l = g_csr[beg + b0 + lane];
            n_l = g_nrm[beg + b0 + lane];
        }
        for (int j = 0; j < n; j++) {
            int   s   = __shfl_sync(0xffffffffu, s_l, j);
            float nrm = __shfl_sync(0xffffffffu, n_l, j);
            const float4* row = (const float4*)(in + (size_t)s * F);
#pragma unroll
            for (int i = 0; i < RF; i++) {
                float4 v = row[i * 32 + lane];
                acc[i].x = fmaf(nrm, v.x, acc[i].x);
                acc[i].y = fmaf(nrm, v.y, acc[i].y);
                acc[i].z = fmaf(nrm, v.z, acc[i].z);
                acc[i].w = fmaf(nrm, v.w, acc[i].w);
            }
        }
    }

    {
        float dd = g_dinv[d];
        float nrm = dd * dd;
        const float4* row = (const float4*)(in + (size_t)d * F);
#pragma unroll
        for (int i = 0; i < RF; i++) {
            float4 v = row[i * 32 + lane];
            acc[i].x = fmaf(nrm, v.x, acc[i].x);
            acc[i].y = fmaf(nrm, v.y, acc[i].y);
            acc[i].z = fmaf(nrm, v.z, acc[i].z);
            acc[i].w = fmaf(nrm, v.w, acc[i].w);
        }
    }

    float4* op = (float4*)(out + (size_t)d * F);
#pragma unroll
    for (int i = 0; i < RF; i++) op[i * 32 + lane] = acc[i];
}

// ---------------- standalone bias + LN + ELU (block per node) ---------------
template<int F>
__global__ void ln_elu_k(const float* __restrict__ in,
                         const float* __restrict__ bias,
                         const float* __restrict__ gamma,
                         const float* __restrict__ beta,
                         float* __restrict__ out)
{
    int node = blockIdx.x;
    int tid = threadIdx.x;
    constexpr int NT = F / 4;
    constexpr int NW = NT / 32;
    const float4* row = (const float4*)(in + (size_t)node * F);
    float4 v = row[tid];
    float4 bb = ((const float4*)bias)[tid];
    v.x += bb.x; v.y += bb.y; v.z += bb.z; v.w += bb.w;
    float s = v.x + v.y + v.z + v.w;
    float q = v.x * v.x + v.y * v.y + v.z * v.z + v.w * v.w;
#pragma unroll
    for (int o = 16; o > 0; o >>= 1) {
        s += __shfl_xor_sync(0xffffffffu, s, o);
        q += __shfl_xor_sync(0xffffffffu, q, o);
    }
    __shared__ float ss[NW], sq[NW];
    int wid = tid >> 5, lane = tid & 31;
    if (NW > 1) {
        if (lane == 0) { ss[wid] = s; sq[wid] = q; }
        __syncthreads();
        s = 0.f; q = 0.f;
#pragma unroll
        for (int w = 0; w < NW; w++) { s += ss[w]; q += sq[w]; }
    }
    constexpr float invF = 1.0f / F;
    float mu = s * invF;
    float var = q * invF - mu * mu;
    float rstd = rsqrtf(var + 1e-5f);
    float4 gv = ((const float4*)gamma)[tid];
    float4 bv = ((const float4*)beta)[tid];
    float4 y;
    y.x = (v.x - mu) * rstd * gv.x + bv.x;
    y.y = (v.y - mu) * rstd * gv.y + bv.y;
    y.z = (v.z - mu) * rstd * gv.z + bv.z;
    y.w = (v.w - mu) * rstd * gv.w + bv.w;
    float4 eo;
    eo.x = y.x > 0.f ? y.x : expm1f(y.x);
    eo.y = y.y > 0.f ? y.y : expm1f(y.y);
    eo.z = y.z > 0.f ? y.z : expm1f(y.z);
    eo.w = y.w > 0.f ? y.w : expm1f(y.w);
    ((float4*)(out + (size_t)node * F))[tid] = eo;
}

// ---------------- host launch ----------------------------------------------
static inline void* sym(const void* s) {
    void* p = nullptr;
    cudaGetSymbolAddress(&p, s);
    return p;
}

extern "C" void kernel_launch(void* const* d_in, const int* in_sizes, int n_in,
                              void* d_out, int out_size) {
    const float* x  = (const float*)d_in[0];
    const unsigned int* e = (const unsigned int*)d_in[1];
    const float* W1 = (const float*)d_in[2];  const float* b1 = (const float*)d_in[3];
    const float* W2 = (const float*)d_in[4];  const float* b2 = (const float*)d_in[5];
    const float* W3 = (const float*)d_in[6];  const float* b3 = (const float*)d_in[7];
    const float* W4 = (const float*)d_in[8];  const float* b4 = (const float*)d_in[9];
    const float* Wc = (const float*)d_in[10]; const float* bc = (const float*)d_in[11];
    const float* g1 = (const float*)d_in[12]; const float* be1 = (const float*)d_in[13];
    const float* g2 = (const float*)d_in[14]; const float* be2 = (const float*)d_in[15];
    const float* g3 = (const float*)d_in[16]; const float* be3 = (const float*)d_in[17];
    const float* g4 = (const float*)d_in[18]; const float* be4 = (const float*)d_in[19];

    long long E = (long long)in_sizes[1] / 2;

    float* out        = (float*)d_out;
    float* out_logits = out;
    float* out_conv   = out + (size_t)NN * 4;
    float* out_bn     = out_conv + (size_t)NN * 128;

    float* xw   = (float*)sym(g_xw);
    float* h1   = (float*)sym(g_h1);
    float* h2   = (float*)sym(g_h2);
    float* h4in = (float*)sym(g_h4in);
    __nv_bfloat16* whi = (__nv_bfloat16*)sym(g_whi);
    __nv_bfloat16* wlo = (__nv_bfloat16*)sym(g_wlo);

    static cudaStream_t s2 = nullptr;
    static cudaEvent_t ev1 = nullptr, ev2 = nullptr;
    if (s2 == nullptr) {
        cudaStreamCreateWithFlags(&s2, cudaStreamNonBlocking);
        cudaEventCreateWithFlags(&ev1, cudaEventDisableTiming);
        cudaEventCreateWithFlags(&ev2, cudaEventDisableTiming);
        cudaFuncSetAttribute(gemm_bf16x2_k,
                             cudaFuncAttributeMaxDynamicSharedMemorySize, 65536);
    }

    int mgrid = (NN + 127) / 128;   // 391
    unsigned agg_blocks = (NN * 32 + 255) / 256;

    // ---- fork: CSR build + W2..W4 split on s2, overlapped with L1 GEMM ----
    cudaEventRecord(ev1, 0);
    cudaStreamWaitEvent(s2, ev1, 0);

    detect_k<<<1, 256, 0, s2>>>(e);
    zero_deg_k<<<(NN + 255) / 256, 256, 0, s2>>>();
    hist_k<<<(unsigned)((E + 255) / 256), 256, 0, s2>>>(e, E);
    dinv_k<<<(NN + 255) / 256, 256, 0, s2>>>();
    scan1_k<<<NB, SCAN_B, 0, s2>>>();
    scan2_k<<<1, 32, 0, s2>>>();
    scan3_k<<<(NN + 255) / 256, 256, 0, s2>>>();
    fill_k<<<(unsigned)((E + 255) / 256), 256, 0, s2>>>(e, E);
    wsplit_k<<<(256 * 512 + 255) / 256, 256, 0, s2>>>(W2, 256, 512, 131072);
    wsplit_k<<<(512 * 256 + 255) / 256, 256, 0, s2>>>(W3, 512, 256, 262144);
    wsplit_k<<<(256 * 128 + 255) / 256, 256, 0, s2>>>(W4, 256, 128, 393216);
    cudaEventRecord(ev2, s2);

    // main stream: W1 split + layer-1 GEMM run concurrently with s2
    wsplit_k<<<(512 * 256 + 255) / 256, 256>>>(W1, 512, 256, 0);
    gemm_bf16x2_k<<<dim3(2, mgrid), 256, 65536>>>(x, whi, wlo, xw, NN, 256, 512);

    cudaStreamWaitEvent(0, ev2, 0);

    // ---- layer 1: agg + LN + ELU -> h1 ----
    agg_ln_elu_k<256><<<agg_blocks, 256>>>(xw, b1, g1, be1, h1, nullptr, nullptr, nullptr);

    // ---- layer 2 (agg-first): tmp = A_hat h1; gemm; LN+ELU -> h2 ----
    agg_only_k<256><<<agg_blocks, 256>>>(h1, h4in);
    gemm_bf16x2_k<<<dim3(4, mgrid), 256, 65536>>>(h4in, whi + 131072, wlo + 131072,
                                                  xw, NN, 512, 256);
    ln_elu_k<512><<<NN, 128>>>(xw, b2, g2, be2, h2);

    // ---- layer 3: gemm(h2)@W3; agg + LN + ELU + residual(h1) -> h4in ----
    gemm_bf16x2_k<<<dim3(2, mgrid), 256, 65536>>>(h2, whi + 262144, wlo + 262144,
                                                  xw, NN, 256, 512);
    agg_ln_elu_k<256><<<agg_blocks, 256>>>(xw, b3, g3, be3, h4in, h1, nullptr, nullptr);

    // ---- layer 4: gemm(h4in)@W4; agg + LN + ELU + fused classifier ----
    gemm_bf16x2_k<<<dim3(1, mgrid), 256, 65536>>>(h4in, whi + 393216, wlo + 393216,
                                                  xw, NN, 128, 256);
    agg_ln_elu_k<128><<<agg_blocks, 256>>>(xw, b4, g4, be4, nullptr, nullptr,
                                           out_conv, out_bn, Wc, bc, out_logits);
}